// round 13
// baseline (speedup 1.0000x reference)
#include <cuda_runtime.h>
#include <cuda_bf16.h>

#define TT 200
#define BB 256

// ---------------- scratch (device globals: allocation-free) ----------------
__device__ float d_whhp[4][1024*256];           // permuted Whh
__device__ float d_cihp[2][1024*30];            // permuted char Wih
__device__ float d_wihp[2][1024*128];           // permuted word Wih
__device__ float d_bp[4][1024];                 // permuted biases
__device__ __nv_bfloat16 d_hbuf[4*2*BB*256];    // ping-pong h per dir (bf16)
__device__ __nv_bfloat16 d_char_h[BB*TT*512];   // [b][t][512] bf16
__device__ __nv_bfloat16 d_word_h[BB*TT*512];   // [b][w][512] bf16
__device__ __nv_bfloat16 d_xcat[BB*TT*712];     // concat bf16
__device__ __nv_bfloat16 d_buf1[BB*TT*512];
__device__ __nv_bfloat16 d_buf2[BB*TT*256];
__device__ float d_logits[BB*TT*12];
__device__ float d_crf[2*BB];

__device__ unsigned g_arrs[16];
__device__ volatile unsigned g_gens[16];

__device__ __forceinline__ float sp_(float x) { return fmaxf(x, 0.f) + log1pf(expf(-fabsf(x))); }
__device__ __forceinline__ float sg_(float x) { return 1.f / (1.f + expf(-x)); }

// pack two fp32 -> bf16x2 word (lo = first element)
__device__ __forceinline__ unsigned pk2(float lo, float hi) {
    unsigned r;
    asm("cvt.rn.bf16x2.f32 %0, %1, %2;" : "=r"(r) : "f"(hi), "f"(lo));
    return r;
}

__device__ __forceinline__ void mma_bf16(float* d, const unsigned* a, const unsigned* b) {
    asm volatile(
        "mma.sync.aligned.m16n8k16.row.col.f32.bf16.bf16.f32 "
        "{%0,%1,%2,%3}, {%4,%5,%6,%7}, {%8,%9}, {%0,%1,%2,%3};\n"
        : "+f"(d[0]), "+f"(d[1]), "+f"(d[2]), "+f"(d[3])
        : "r"(a[0]), "r"(a[1]), "r"(a[2]), "r"(a[3]), "r"(b[0]), "r"(b[1]));
}

// mma-friendly gate-column permutation: (g,u) -> permuted row index
__device__ __forceinline__ int perm_gu(int g, int u) {
    int nb = u >> 4, w16 = u & 15;
    int h = w16 >> 3, v = w16 & 7;
    int p = v >> 2, t = v & 3;
    return nb * 64 + h * 32 + p * 16 + ((g >> 1) << 3) + t * 2 + (g & 1);
}

// ---------------- init + fused prep ----------------
__global__ void k_init(__nv_bfloat16* hbuf) {
    int i = blockIdx.x * blockDim.x + threadIdx.x;
    if (i < 16) { g_arrs[i] = 0; g_gens[i] = 0; }
    if (i < 4 * 2 * BB * 128) ((unsigned*)hbuf)[i] = 0u;
}

struct PrepP {
    const float* whh[4];
    const float* cih[2];
    const float* wih[2];
    const float* bias[4];
    float* whhp; float* cihp; float* wihp; float* bp;
};

// y: 0-3 Whh(K=256), 4-5 char Wih(K=30), 6-7 word Wih(K=128), 8-11 bias
__global__ void k_prep(PrepP p) {
    int y = blockIdx.y;
    int i = blockIdx.x * blockDim.x + threadIdx.x;
    if (y < 4) {
        if (i >= 1024 * 256) return;
        int k = i & 255, s = i >> 8;
        int g = s >> 8, u = s & 255;
        p.whhp[(size_t)y * 262144 + perm_gu(g, u) * 256 + k] = p.whh[y][(size_t)s * 256 + k];
    } else if (y < 6) {
        if (i >= 1024 * 30) return;
        int k = i % 30, s = i / 30;
        int g = s >> 8, u = s & 255;
        p.cihp[(size_t)(y - 4) * 30720 + perm_gu(g, u) * 30 + k] = p.cih[y - 4][(size_t)s * 30 + k];
    } else if (y < 8) {
        if (i >= 1024 * 128) return;
        int k = i & 127, s = i >> 7;
        int g = s >> 8, u = s & 255;
        p.wihp[(size_t)(y - 6) * 131072 + perm_gu(g, u) * 128 + k] = p.wih[y - 6][(size_t)s * 128 + k];
    } else {
        if (i >= 1024) return;
        int g = i >> 8, u = i & 255;
        p.bp[(y - 8) * 1024 + perm_gu(g, u)] = p.bias[y - 8][i];
    }
}

// ---------------- BF16 tensor-core GEMM (double-buffered, 1 sync/chunk) ----------------
// C = act(A[M,K] @ W[N,K]^T + bias); block 128(M) x 64(N); 8 warps 32x32 each.
// A bf16; obf: bf16 output. M multiple of 128.
__global__ void __launch_bounds__(256) k_gemm_tc(
        const __nv_bfloat16* __restrict__ Ab, const float* __restrict__ W,
        const float* __restrict__ bias, float* __restrict__ C,
        int M, int N, int K, int ldc, int act, int obf) {
    __shared__ unsigned As[2][128][20];
    __shared__ unsigned Bs[2][64][20];

    int tid = threadIdx.x;
    int bm = blockIdx.y * 128, bn = blockIdx.x * 64;
    int wid = tid >> 5, lane = tid & 31;
    int wm = (wid & 3) * 32, wn = (wid >> 2) * 32;
    int gid = lane >> 2, tig = lane & 3;
    bool k4 = (K & 3) == 0;

    float acc[2][4][4];
#pragma unroll
    for (int i = 0; i < 2; i++)
#pragma unroll
        for (int j = 0; j < 4; j++)
#pragma unroll
            for (int v = 0; v < 4; v++) acc[i][j][v] = 0.f;

    uint4 rau[2];
    float rb[8];

    auto load_stage = [&](int k0) {
#pragma unroll
        for (int j = 0; j < 2; j++) {
            int q = tid + 256 * j;
            int r = q >> 2, cw4 = (q & 3) * 4;
            int ke = k0 + cw4 * 2;
            const __nv_bfloat16* src = Ab + (size_t)(bm + r) * K + ke;
            if (ke + 8 <= K) rau[j] = *(const uint4*)src;
            else {
                unsigned w[4] = {0u, 0u, 0u, 0u};
#pragma unroll
                for (int e = 0; e < 8; e++)
                    if (ke + e < K) ((__nv_bfloat16*)w)[e] = src[e];
                rau[j] = make_uint4(w[0], w[1], w[2], w[3]);
            }
        }
#pragma unroll
        for (int j = 0; j < 2; j++) {
            int q = tid + 256 * j;
            int r = q >> 3, c = (q & 7) * 4;
            float4 v = make_float4(0.f, 0.f, 0.f, 0.f);
            if (bn + r < N) {
                const float* src = W + (size_t)(bn + r) * K + k0 + c;
                if (k4 && k0 + c + 3 < K) v = *(const float4*)src;
                else {
                    v.x = (k0 + c + 0 < K) ? src[0] : 0.f;
                    v.y = (k0 + c + 1 < K) ? src[1] : 0.f;
                    v.z = (k0 + c + 2 < K) ? src[2] : 0.f;
                    v.w = (k0 + c + 3 < K) ? src[3] : 0.f;
                }
            }
            rb[j * 4 + 0] = v.x; rb[j * 4 + 1] = v.y; rb[j * 4 + 2] = v.z; rb[j * 4 + 3] = v.w;
        }
    };

    auto store_stage = [&](int s) {
#pragma unroll
        for (int j = 0; j < 2; j++) {
            int q = tid + 256 * j;
            int r = q >> 2, cw4 = (q & 3) * 4;
            *(uint4*)&As[s][r][cw4] = rau[j];
        }
#pragma unroll
        for (int j = 0; j < 2; j++) {
            int q = tid + 256 * j;
            int r = q >> 3, cw = (q & 7) * 2;
            *(uint2*)&Bs[s][r][cw] = make_uint2(pk2(rb[j*4+0], rb[j*4+1]), pk2(rb[j*4+2], rb[j*4+3]));
        }
    };

    int nch = (K + 31) / 32;
    load_stage(0);
    store_stage(0);
    if (nch > 1) load_stage(32);
    __syncthreads();

    for (int i = 0; i < nch; i++) {
        if (i + 1 < nch) {
            store_stage((i + 1) & 1);          // regs hold chunk i+1
            if (i + 2 < nch) load_stage((i + 2) * 32);
        }
        int s = i & 1;
#pragma unroll
        for (int ks = 0; ks < 2; ks++) {
            int kw = ks * 8;
            unsigned af[2][4], bf[4][2];
#pragma unroll
            for (int im = 0; im < 2; im++) {
                int rm = wm + im * 16;
                af[im][0] = As[s][rm + gid][kw + tig];
                af[im][1] = As[s][rm + gid + 8][kw + tig];
                af[im][2] = As[s][rm + gid][kw + tig + 4];
                af[im][3] = As[s][rm + gid + 8][kw + tig + 4];
            }
#pragma unroll
            for (int jn = 0; jn < 4; jn++) {
                int cn = wn + jn * 8;
                bf[jn][0] = Bs[s][cn + gid][kw + tig];
                bf[jn][1] = Bs[s][cn + gid][kw + tig + 4];
            }
#pragma unroll
            for (int im = 0; im < 2; im++)
#pragma unroll
                for (int jn = 0; jn < 4; jn++)
                    mma_bf16(acc[im][jn], af[im], bf[jn]);
        }
        __syncthreads();
    }

#pragma unroll
    for (int im = 0; im < 2; im++) {
#pragma unroll
        for (int jn = 0; jn < 4; jn++) {
            int row0 = bm + wm + im * 16 + gid;
            int col0 = bn + wn + jn * 8 + tig * 2;
#pragma unroll
            for (int half = 0; half < 2; half++) {
                int row = row0 + half * 8;
                if (obf) {
                    if (col0 < N) {
                        float v0 = acc[im][jn][half * 2 + 0];
                        float v1 = acc[im][jn][half * 2 + 1];
                        if (bias) { v0 += bias[col0]; v1 += bias[col0 + 1]; }
                        if (act) { v0 = sp_(v0); v1 = sp_(v1); }
                        *(unsigned*)(((__nv_bfloat16*)C) + (size_t)row * ldc + col0) = pk2(v0, v1);
                    }
                } else {
#pragma unroll
                    for (int cc = 0; cc < 2; cc++) {
                        int col = col0 + cc;
                        if (col >= N) continue;
                        float v = acc[im][jn][half * 2 + cc];
                        if (bias) v += bias[col];
                        if (act) v = sp_(v);
                        C[(size_t)row * ldc + col] = v;
                    }
                }
            }
        }
    }
}

// ---------------- persistent recurrence (bf16 tensor cores, fused input proj) ----------------
struct RP {
    const float* whhp;      // [4][1024*256] permuted
    const float* cihp;      // [2][1024*30]  permuted
    const float* wihp;      // [2][1024*128] permuted
    const float* bp;        // [4][1024]     permuted
    const int*   chars;     // [B][T]
    const float* emb;       // [V][30]
    const float* words;     // [B][WN][128]
    __nv_bfloat16* hbuf;    // bf16 ping-pong
    const int* len_char;
    const int* len_word;
    __nv_bfloat16* outc;
    __nv_bfloat16* outw;
};

// per-(dir,mb) barrier over 16 blocks
__device__ __forceinline__ void grid_bar(int gi, unsigned target) {
    __threadfence();
    __syncthreads();
    if (threadIdx.x == 0) {
        if (atomicAdd(&g_arrs[gi], 1u) == 15u) {
            g_arrs[gi] = 0;
            __threadfence();
            g_gens[gi] = target;
        } else {
            while (g_gens[gi] < target) __nanosleep(32);
        }
    }
    __syncthreads();
}

// smem: Ws [64][132] + As [64][132] + Wxs [64][68] + Xs [64][68] (words)
#define REC_SMEM ((64*132*2 + 64*68*2) * 4)   // 102400 B

__global__ void __launch_bounds__(256, 2) k_rec_persist(RP p) {
    extern __shared__ unsigned smu[];
    unsigned* Ws  = smu;                       // [64][132] Whh tile
    unsigned* As  = Ws  + 64 * 132;            // [64][132] h tile
    unsigned* Wxs = As  + 64 * 132;            // [64][68]  Wih tile
    unsigned* Xs  = Wxs + 64 * 68;             // [64][68]  x tile

    int bx = blockIdx.x;
    int dir = bx >> 6, mb = (bx >> 4) & 3, nb = bx & 15;
    int gi = dir * 4 + mb;
    int tid = threadIdx.x;
    int wid = tid >> 5, lane = tid & 31;
    int gid = lane >> 2, tig = lane & 3;
    int wm = (wid & 3) * 16;
    int wnh = wid >> 2;
    int bm = mb * 64;

    int Kx  = (dir < 2) ? 30 : 128;
    int Kxw = (dir < 2) ? 16 : 64;
    const float* Wx = (dir < 2) ? (p.cihp + (size_t)dir * 1024 * 30)
                                : (p.wihp + (size_t)(dir - 2) * 1024 * 128);

    // load + pack Whh tile [64 cols][256 k]
    const float* W = p.whhp + (size_t)dir * 1024 * 256;
    for (int idx = tid; idx < 64 * 128; idx += 256) {
        int n = idx >> 7, kw = idx & 127;
        float2 v = *(const float2*)&W[(size_t)(nb * 64 + n) * 256 + kw * 2];
        Ws[n * 132 + kw] = pk2(v.x, v.y);
    }
    // load + pack Wih tile [64 cols][Kx k] (zero-padded to Kxw words)
    for (int idx = tid; idx < 64 * Kxw; idx += 256) {
        int n = idx / Kxw, kw = idx % Kxw;
        const float* wr = Wx + (size_t)(nb * 64 + n) * Kx;
        float lo = (kw * 2     < Kx) ? wr[kw * 2]     : 0.f;
        float hi = (kw * 2 + 1 < Kx) ? wr[kw * 2 + 1] : 0.f;
        Wxs[n * 68 + kw] = pk2(lo, hi);
    }

    // bias fragment: col = nb*64 + wnh*32 + jn*8 + tig*2 + c
    const float* bpd = p.bp + dir * 1024 + nb * 64 + wnh * 32;
    float bias_r[4][2];
#pragma unroll
    for (int jn = 0; jn < 4; jn++) {
        bias_r[jn][0] = bpd[jn * 8 + tig * 2];
        bias_r[jn][1] = bpd[jn * 8 + tig * 2 + 1];
    }

    float hreg[2][2], creg[2][2];
#pragma unroll
    for (int i = 0; i < 2; i++)
#pragma unroll
        for (int j = 0; j < 2; j++) { hreg[i][j] = 0.f; creg[i][j] = 0.f; }

    const int* lens = (dir < 2) ? p.len_char : p.len_word;
    int lenv[2];
    lenv[0] = lens[bm + wm + gid];
    lenv[1] = lens[bm + wm + gid + 8];

    __nv_bfloat16* hb0 = p.hbuf + (size_t)dir * 2 * 65536;
    __nv_bfloat16* hb1 = hb0 + 65536;
    __nv_bfloat16* outp = (dir < 2) ? p.outc : p.outw;
    int half = (dir & 1) ? 256 : 0;

    __syncthreads();

    for (int t = 0; t < TT; t++) {
        int tr = (dir & 1) ? (TT - 1 - t) : t;
        const __nv_bfloat16* h = (t & 1) ? hb1 : hb0;
        __nv_bfloat16* hn_buf = (t & 1) ? hb0 : hb1;

        // stage h tile [64 rows][256 k] — pure uint4 copy (already bf16)
#pragma unroll
        for (int j = 0; j < 8; j++) {
            int q = tid + 256 * j;
            int r = q >> 5, c4 = q & 31;
            uint4 v = __ldcg((const uint4*)&h[(bm + r) * 256 + c4 * 8]);
            *(uint4*)&As[r * 132 + c4 * 4] = v;
        }
        // stage x tile [64 rows][Kx] — read inputs directly (no staging buffers)
        if (Kxw == 64) {
            // word: row (b, tr) = 128 contiguous floats in words[b][tr][*]
#pragma unroll
            for (int j = 0; j < 8; j++) {
                int q = tid + 256 * j;
                int r = q >> 5, c4 = q & 31;
                const float* wr = p.words + ((size_t)(bm + r) * TT + tr) * 128 + c4 * 4;
                float4 v = __ldg((const float4*)wr);
                *(uint2*)&Xs[r * 68 + c4 * 2] = make_uint2(pk2(v.x, v.y), pk2(v.z, v.w));
            }
        } else {
            // char: inline embedding gather (30 contiguous floats per row)
#pragma unroll
            for (int j = 0; j < 4; j++) {
                int q = tid + 256 * j;
                int r = q >> 4, kw = q & 15;
                int ci = __ldg(&p.chars[(bm + r) * TT + tr]);
                const float* xr = p.emb + (size_t)ci * 30;
                float lo = (kw * 2     < 30) ? xr[kw * 2]     : 0.f;
                float hi = (kw * 2 + 1 < 30) ? xr[kw * 2 + 1] : 0.f;
                Xs[r * 68 + kw] = pk2(lo, hi);
            }
        }
        __syncthreads();

        float acc[4][4];
#pragma unroll
        for (int j = 0; j < 4; j++)
#pragma unroll
            for (int v = 0; v < 4; v++) acc[j][v] = 0.f;

        // h @ Whh^T
#pragma unroll
        for (int ks = 0; ks < 16; ks++) {
            int kw = ks * 8;
            unsigned af[4], bf[4][2];
            af[0] = As[(wm + gid) * 132 + kw + tig];
            af[1] = As[(wm + gid + 8) * 132 + kw + tig];
            af[2] = As[(wm + gid) * 132 + kw + tig + 4];
            af[3] = As[(wm + gid + 8) * 132 + kw + tig + 4];
#pragma unroll
            for (int jn = 0; jn < 4; jn++) {
                int n0 = wnh * 32 + jn * 8;
                bf[jn][0] = Ws[(n0 + gid) * 132 + kw + tig];
                bf[jn][1] = Ws[(n0 + gid) * 132 + kw + tig + 4];
            }
#pragma unroll
            for (int jn = 0; jn < 4; jn++)
                mma_bf16(acc[jn], af, bf[jn]);
        }
        // x @ Wih^T (fused input projection)
        int nksx = Kxw >> 3;
#pragma unroll 2
        for (int ks = 0; ks < nksx; ks++) {
            int kw = ks * 8;
            unsigned af[4], bf[4][2];
            af[0] = Xs[(wm + gid) * 68 + kw + tig];
            af[1] = Xs[(wm + gid + 8) * 68 + kw + tig];
            af[2] = Xs[(wm + gid) * 68 + kw + tig + 4];
            af[3] = Xs[(wm + gid + 8) * 68 + kw + tig + 4];
#pragma unroll
            for (int jn = 0; jn < 4; jn++) {
                int n0 = wnh * 32 + jn * 8;
                bf[jn][0] = Wxs[(n0 + gid) * 68 + kw + tig];
                bf[jn][1] = Wxs[(n0 + gid) * 68 + kw + tig + 4];
            }
#pragma unroll
            for (int jn = 0; jn < 4; jn++)
                mma_bf16(acc[jn], af, bf[jn]);
        }

        // fused LSTM cell epilogue (bias folded); h stored as bf16
#pragma unroll
        for (int rh = 0; rh < 2; rh++) {
            int b = bm + wm + gid + rh * 8;
            bool valid = tr < lenv[rh];
#pragma unroll
            for (int pp = 0; pp < 2; pp++) {
                float gi_ = acc[2 * pp + 0][rh * 2 + 0] + bias_r[2 * pp + 0][0];
                float gf = acc[2 * pp + 0][rh * 2 + 1] + bias_r[2 * pp + 0][1];
                float gc = acc[2 * pp + 1][rh * 2 + 0] + bias_r[2 * pp + 1][0];
                float go = acc[2 * pp + 1][rh * 2 + 1] + bias_r[2 * pp + 1][1];
                float cn = sg_(gf) * creg[rh][pp] + sg_(gi_) * tanhf(gc);
                float hv = sg_(go) * tanhf(cn);
                if (valid) { creg[rh][pp] = cn; hreg[rh][pp] = hv; }
                int u = nb * 16 + wnh * 8 + pp * 4 + tig;
                outp[((size_t)b * TT + tr) * 512 + half + u] = __float2bfloat16(valid ? hv : 0.f);
                hn_buf[b * 256 + u] = __float2bfloat16(hreg[rh][pp]);
            }
        }

        if (t + 1 < TT) grid_bar(gi, (unsigned)(t + 1));
    }
}

// ---------------- CRF: real path score (one warp per batch, deterministic) ----------------
__global__ void k_crf_real(const float* __restrict__ logits, const int* __restrict__ tags,
                           const int* __restrict__ lens, const float* __restrict__ trans,
                           float* __restrict__ rl) {
    __shared__ float st[144];
    int tid = threadIdx.x;
    if (tid < 144) st[tid] = trans[tid];
    __syncthreads();
    int warp = tid >> 5, lane = tid & 31;
    int b = blockIdx.x * 8 + warp;
    int len = lens[b];
    float s = 0.f;
    for (int t = lane; t < len; t += 32) {
        int tg = tags[b * TT + t];
        int prev = (t == 0) ? 10 : tags[b * TT + t - 1];
        s += logits[((size_t)b * TT + t) * 12 + tg] + st[prev * 12 + tg];
    }
#pragma unroll
    for (int o = 16; o > 0; o >>= 1) s += __shfl_xor_sync(0xffffffffu, s, o);
    if (lane == 0) {
        int last = tags[b * TT + len - 1];
        rl[b] = s + st[last * 12 + 11];
    }
}

// ---------------- CRF forward: one warp per batch ----------------
__global__ void k_crf_fwd(const float* __restrict__ logits, const int* __restrict__ lens,
                          const float* __restrict__ trans, float* __restrict__ tot) {
    __shared__ float st[144];
    int tid = threadIdx.x;
    if (tid < 144) st[tid] = trans[tid];
    __syncthreads();
    int warp = tid >> 5, lane = tid & 31;
    int b = blockIdx.x * 8 + warp;
    int len = lens[b];
    float alpha = 0.f;
    for (int t = 0; t < TT; t++) {
        float lt = (lane < 12) ? logits[((size_t)b * TT + t) * 12 + lane] : 0.f;
        float sc[12];
        float mx = -1e30f;
#pragma unroll
        for (int i = 0; i < 12; i++) {
            float ai = __shfl_sync(0xffffffffu, alpha, i);
            float s = ai + ((lane < 12) ? st[i * 12 + lane] : 0.f);
            sc[i] = s;
            mx = fmaxf(mx, s);
        }
        float sm = 0.f;
#pragma unroll
        for (int i = 0; i < 12; i++) sm += expf(sc[i] - mx);
        float an = mx + logf(sm) + lt;
        if (t < len) alpha = an;
    }
    float v = (lane < 12) ? alpha + st[lane * 12 + 11] : -1e30f;
    float mx = v;
#pragma unroll
    for (int o = 16; o > 0; o >>= 1) mx = fmaxf(mx, __shfl_xor_sync(0xffffffffu, mx, o));
    float e = expf(v - mx);
#pragma unroll
    for (int o = 16; o > 0; o >>= 1) e += __shfl_xor_sync(0xffffffffu, e, o);
    if (lane == 0) tot[b] = mx + logf(e);
}

__global__ void k_crf_reduce(const float* __restrict__ crf, float* __restrict__ out) {
    __shared__ float s[256];
    int t = threadIdx.x;
    s[t] = crf[t] - crf[256 + t];
    __syncthreads();
    for (int o = 128; o > 0; o >>= 1) {
        if (t < o) s[t] += s[t + o];
        __syncthreads();
    }
    if (t == 0) out[0] = s[0];
}

// ---------------- launch ----------------
extern "C" void kernel_launch(void* const* d_in, const int* in_sizes, int n_in,
                              void* d_out, int out_size) {
    const int*   characters = (const int*)d_in[0];
    const float* words      = (const float*)d_in[1];
    const int*   tags       = (const int*)d_in[2];
    const int*   len_char   = (const int*)d_in[3];
    const int*   len_word   = (const int*)d_in[4];
    const float* char_emb   = (const float*)d_in[5];
    const float* cWihf = (const float*)d_in[6];
    const float* cWhhf = (const float*)d_in[7];
    const float* cbf   = (const float*)d_in[8];
    const float* cWihb = (const float*)d_in[9];
    const float* cWhhb = (const float*)d_in[10];
    const float* cbb   = (const float*)d_in[11];
    const float* clinW = (const float*)d_in[12];
    const float* clinb = (const float*)d_in[13];
    const float* wWihf = (const float*)d_in[14];
    const float* wWhhf = (const float*)d_in[15];
    const float* wbf   = (const float*)d_in[16];
    const float* wWihb = (const float*)d_in[17];
    const float* wWhhb = (const float*)d_in[18];
    const float* wbb   = (const float*)d_in[19];
    const float* wlinW = (const float*)d_in[20];
    const float* wlinb = (const float*)d_in[21];
    const float* l1W   = (const float*)d_in[22];
    const float* l1b   = (const float*)d_in[23];
    const float* l2W   = (const float*)d_in[24];
    const float* l2b   = (const float*)d_in[25];
    const float* tW    = (const float*)d_in[26];
    const float* tb    = (const float*)d_in[27];
    const float* trans = (const float*)d_in[28];
    float* out = (float*)d_out;

    float *whhp, *cihp, *wihp, *bp, *logits, *crfb;
    __nv_bfloat16 *hbuf, *char_h, *word_h, *xcat, *buf1, *buf2;
    cudaGetSymbolAddress((void**)&whhp,   d_whhp);
    cudaGetSymbolAddress((void**)&cihp,   d_cihp);
    cudaGetSymbolAddress((void**)&wihp,   d_wihp);
    cudaGetSymbolAddress((void**)&bp,     d_bp);
    cudaGetSymbolAddress((void**)&hbuf,   d_hbuf);
    cudaGetSymbolAddress((void**)&char_h, d_char_h);
    cudaGetSymbolAddress((void**)&word_h, d_word_h);
    cudaGetSymbolAddress((void**)&xcat,   d_xcat);
    cudaGetSymbolAddress((void**)&buf1,   d_buf1);
    cudaGetSymbolAddress((void**)&buf2,   d_buf2);
    cudaGetSymbolAddress((void**)&logits, d_logits);
    cudaGetSymbolAddress((void**)&crfb,   d_crf);

    cudaFuncSetAttribute(k_rec_persist, cudaFuncAttributeMaxDynamicSharedMemorySize, REC_SMEM);

    k_init<<<(4 * 2 * BB * 128 + 255) / 256, 256>>>(hbuf);

    // fused weight/bias permutation (12 ops in one launch)
    PrepP pp;
    pp.whh[0] = cWhhf; pp.whh[1] = cWhhb; pp.whh[2] = wWhhf; pp.whh[3] = wWhhb;
    pp.cih[0] = cWihf; pp.cih[1] = cWihb;
    pp.wih[0] = wWihf; pp.wih[1] = wWihb;
    pp.bias[0] = cbf; pp.bias[1] = cbb; pp.bias[2] = wbf; pp.bias[3] = wbb;
    pp.whhp = whhp; pp.cihp = cihp; pp.wihp = wihp; pp.bp = bp;
    k_prep<<<dim3(1024, 12), 256>>>(pp);

    // persistent recurrence with fused input projections; reads raw inputs directly
    RP rp;
    rp.whhp = whhp;
    rp.cihp = cihp;
    rp.wihp = wihp;
    rp.bp   = bp;
    rp.chars = characters;
    rp.emb   = char_emb;
    rp.words = words;
    rp.hbuf = hbuf;
    rp.len_char = len_char;
    rp.len_word = len_word;
    rp.outc = char_h;
    rp.outw = word_h;
    k_rec_persist<<<256, 256, REC_SMEM>>>(rp);

    int Mbt = BB * TT;  // 51200
    auto grid = [](int M, int N) { return dim3((unsigned)((N + 63) / 64), (unsigned)((M + 127) / 128)); };

    // dense stack (bf16 operands, bf16 intermediates, softplus fused)
    k_gemm_tc<<<grid(Mbt, 512), 256>>>(char_h, clinW, clinb, (float*)xcat,         Mbt, 512, 512, 712, 1, 1);
    k_gemm_tc<<<grid(Mbt, 200), 256>>>(word_h, wlinW, wlinb, (float*)(xcat + 512), Mbt, 200, 512, 712, 1, 1);
    k_gemm_tc<<<grid(Mbt, 512), 256>>>(xcat, l1W, l1b, (float*)buf1, Mbt, 512, 712, 512, 1, 1);
    k_gemm_tc<<<grid(Mbt, 256), 256>>>(buf1, l2W, l2b, (float*)buf2, Mbt, 256, 512, 256, 1, 1);
    k_gemm_tc<<<grid(Mbt, 12),  256>>>(buf2, tW,  tb,  logits,       Mbt, 12,  256, 12,  1, 0);

    // CRF
    k_crf_real<<<32, 256>>>(logits, tags, len_char, trans, crfb + BB);
    k_crf_fwd<<<32, 256>>>(logits, len_char, trans, crfb);
    k_crf_reduce<<<1, 256>>>(crfb, out);
}

// round 14
// speedup vs baseline: 1.0262x; 1.0262x over previous
#include <cuda_runtime.h>
#include <cuda_bf16.h>

#define TT 200
#define BB 256

// ---------------- scratch (device globals: allocation-free) ----------------
__device__ float d_whhp[4][1024*256];           // permuted Whh
__device__ float d_cihp[2][1024*30];            // permuted char Wih
__device__ float d_wihp[2][1024*128];           // permuted word Wih
__device__ float d_bp[4][1024];                 // permuted biases
__device__ __nv_bfloat16 d_hbuf[4*2*BB*256];    // ping-pong h per dir (bf16)
__device__ __nv_bfloat16 d_char_h[BB*TT*512];   // [b][t][512] bf16
__device__ __nv_bfloat16 d_word_h[BB*TT*512];   // [b][w][512] bf16
__device__ __nv_bfloat16 d_xcat[BB*TT*712];     // concat bf16
__device__ __nv_bfloat16 d_buf1[BB*TT*512];
__device__ __nv_bfloat16 d_buf2[BB*TT*256];
__device__ float d_logits[BB*TT*12];
__device__ float d_crf[2*BB];

__device__ unsigned g_arrs[16];
__device__ volatile unsigned g_gens[16];

__device__ __forceinline__ float sp_(float x) { return fmaxf(x, 0.f) + log1pf(expf(-fabsf(x))); }
__device__ __forceinline__ float sg_(float x) { return 1.f / (1.f + expf(-x)); }

// pack two fp32 -> bf16x2 word (lo = first element)
__device__ __forceinline__ unsigned pk2(float lo, float hi) {
    unsigned r;
    asm("cvt.rn.bf16x2.f32 %0, %1, %2;" : "=r"(r) : "f"(hi), "f"(lo));
    return r;
}

__device__ __forceinline__ void mma_bf16(float* d, const unsigned* a, const unsigned* b) {
    asm volatile(
        "mma.sync.aligned.m16n8k16.row.col.f32.bf16.bf16.f32 "
        "{%0,%1,%2,%3}, {%4,%5,%6,%7}, {%8,%9}, {%0,%1,%2,%3};\n"
        : "+f"(d[0]), "+f"(d[1]), "+f"(d[2]), "+f"(d[3])
        : "r"(a[0]), "r"(a[1]), "r"(a[2]), "r"(a[3]), "r"(b[0]), "r"(b[1]));
}

__device__ __forceinline__ unsigned sptr(const void* p) {
    return (unsigned)__cvta_generic_to_shared(p);
}

__device__ __forceinline__ void ldsm_x4(unsigned* r, unsigned addr) {
    asm volatile("ldmatrix.sync.aligned.m8n8.x4.shared.b16 {%0,%1,%2,%3}, [%4];"
        : "=r"(r[0]), "=r"(r[1]), "=r"(r[2]), "=r"(r[3]) : "r"(addr));
}

// mma-friendly gate-column permutation: (g,u) -> permuted row index
__device__ __forceinline__ int perm_gu(int g, int u) {
    int nb = u >> 4, w16 = u & 15;
    int h = w16 >> 3, v = w16 & 7;
    int p = v >> 2, t = v & 3;
    return nb * 64 + h * 32 + p * 16 + ((g >> 1) << 3) + t * 2 + (g & 1);
}

// ---------------- init + fused prep ----------------
__global__ void k_init(__nv_bfloat16* hbuf) {
    int i = blockIdx.x * blockDim.x + threadIdx.x;
    if (i < 16) { g_arrs[i] = 0; g_gens[i] = 0; }
    if (i < 4 * 2 * BB * 128) ((unsigned*)hbuf)[i] = 0u;
}

struct PrepP {
    const float* whh[4];
    const float* cih[2];
    const float* wih[2];
    const float* bias[4];
    float* whhp; float* cihp; float* wihp; float* bp;
};

// y: 0-3 Whh(K=256), 4-5 char Wih(K=30), 6-7 word Wih(K=128), 8-11 bias
__global__ void k_prep(PrepP p) {
    int y = blockIdx.y;
    int i = blockIdx.x * blockDim.x + threadIdx.x;
    if (y < 4) {
        if (i >= 1024 * 256) return;
        int k = i & 255, s = i >> 8;
        int g = s >> 8, u = s & 255;
        p.whhp[(size_t)y * 262144 + perm_gu(g, u) * 256 + k] = p.whh[y][(size_t)s * 256 + k];
    } else if (y < 6) {
        if (i >= 1024 * 30) return;
        int k = i % 30, s = i / 30;
        int g = s >> 8, u = s & 255;
        p.cihp[(size_t)(y - 4) * 30720 + perm_gu(g, u) * 30 + k] = p.cih[y - 4][(size_t)s * 30 + k];
    } else if (y < 8) {
        if (i >= 1024 * 128) return;
        int k = i & 127, s = i >> 7;
        int g = s >> 8, u = s & 255;
        p.wihp[(size_t)(y - 6) * 131072 + perm_gu(g, u) * 128 + k] = p.wih[y - 6][(size_t)s * 128 + k];
    } else {
        if (i >= 1024) return;
        int g = i >> 8, u = i & 255;
        p.bp[(y - 8) * 1024 + perm_gu(g, u)] = p.bias[y - 8][i];
    }
}

// ---------------- BF16 tensor-core GEMM (double-buffered, ldmatrix fragments) ----------------
// C = act(A[M,K] @ W[N,K]^T + bias); block 128(M) x 64(N); 8 warps 32x32 each.
// A bf16; obf: bf16 output. M multiple of 128.
__global__ void __launch_bounds__(256) k_gemm_tc(
        const __nv_bfloat16* __restrict__ Ab, const float* __restrict__ W,
        const float* __restrict__ bias, float* __restrict__ C,
        int M, int N, int K, int ldc, int act, int obf) {
    __shared__ unsigned As[2][128][20];
    __shared__ unsigned Bs[2][64][20];

    int tid = threadIdx.x;
    int bm = blockIdx.y * 128, bn = blockIdx.x * 64;
    int wid = tid >> 5, lane = tid & 31;
    int wm = (wid & 3) * 32, wn = (wid >> 2) * 32;
    int gid = lane >> 2, tig = lane & 3;
    int lr = lane & 15, lc = (lane >> 4) * 4;   // ldmatrix lane addressing
    bool k4 = (K & 3) == 0;

    float acc[2][4][4];
#pragma unroll
    for (int i = 0; i < 2; i++)
#pragma unroll
        for (int j = 0; j < 4; j++)
#pragma unroll
            for (int v = 0; v < 4; v++) acc[i][j][v] = 0.f;

    uint4 rau[2];
    float rb[8];

    auto load_stage = [&](int k0) {
#pragma unroll
        for (int j = 0; j < 2; j++) {
            int q = tid + 256 * j;
            int r = q >> 2, cw4 = (q & 3) * 4;
            int ke = k0 + cw4 * 2;
            const __nv_bfloat16* src = Ab + (size_t)(bm + r) * K + ke;
            if (ke + 8 <= K) rau[j] = *(const uint4*)src;
            else {
                unsigned w[4] = {0u, 0u, 0u, 0u};
#pragma unroll
                for (int e = 0; e < 8; e++)
                    if (ke + e < K) ((__nv_bfloat16*)w)[e] = src[e];
                rau[j] = make_uint4(w[0], w[1], w[2], w[3]);
            }
        }
#pragma unroll
        for (int j = 0; j < 2; j++) {
            int q = tid + 256 * j;
            int r = q >> 3, c = (q & 7) * 4;
            float4 v = make_float4(0.f, 0.f, 0.f, 0.f);
            if (bn + r < N) {
                const float* src = W + (size_t)(bn + r) * K + k0 + c;
                if (k4 && k0 + c + 3 < K) v = *(const float4*)src;
                else {
                    v.x = (k0 + c + 0 < K) ? src[0] : 0.f;
                    v.y = (k0 + c + 1 < K) ? src[1] : 0.f;
                    v.z = (k0 + c + 2 < K) ? src[2] : 0.f;
                    v.w = (k0 + c + 3 < K) ? src[3] : 0.f;
                }
            }
            rb[j * 4 + 0] = v.x; rb[j * 4 + 1] = v.y; rb[j * 4 + 2] = v.z; rb[j * 4 + 3] = v.w;
        }
    };

    auto store_stage = [&](int s) {
#pragma unroll
        for (int j = 0; j < 2; j++) {
            int q = tid + 256 * j;
            int r = q >> 2, cw4 = (q & 3) * 4;
            *(uint4*)&As[s][r][cw4] = rau[j];
        }
#pragma unroll
        for (int j = 0; j < 2; j++) {
            int q = tid + 256 * j;
            int r = q >> 3, cw = (q & 7) * 2;
            *(uint2*)&Bs[s][r][cw] = make_uint2(pk2(rb[j*4+0], rb[j*4+1]), pk2(rb[j*4+2], rb[j*4+3]));
        }
    };

    int nch = (K + 31) / 32;
    load_stage(0);
    store_stage(0);
    if (nch > 1) load_stage(32);
    __syncthreads();

    for (int i = 0; i < nch; i++) {
        if (i + 1 < nch) {
            store_stage((i + 1) & 1);          // regs hold chunk i+1
            if (i + 2 < nch) load_stage((i + 2) * 32);
        }
        int s = i & 1;
#pragma unroll
        for (int ks = 0; ks < 2; ks++) {
            int kw = ks * 8;
            unsigned af[2][4], b0[4], b1[4];
#pragma unroll
            for (int im = 0; im < 2; im++)
                ldsm_x4(af[im], sptr(&As[s][wm + im * 16 + lr][kw + lc]));
            ldsm_x4(b0, sptr(&Bs[s][wn + lane][kw]));
            ldsm_x4(b1, sptr(&Bs[s][wn + lane][kw + 4]));
#pragma unroll
            for (int im = 0; im < 2; im++)
#pragma unroll
                for (int jn = 0; jn < 4; jn++) {
                    unsigned bb[2] = {b0[jn], b1[jn]};
                    mma_bf16(acc[im][jn], af[im], bb);
                }
        }
        __syncthreads();
    }

#pragma unroll
    for (int im = 0; im < 2; im++) {
#pragma unroll
        for (int jn = 0; jn < 4; jn++) {
            int row0 = bm + wm + im * 16 + gid;
            int col0 = bn + wn + jn * 8 + tig * 2;
#pragma unroll
            for (int half = 0; half < 2; half++) {
                int row = row0 + half * 8;
                if (obf) {
                    if (col0 < N) {
                        float v0 = acc[im][jn][half * 2 + 0];
                        float v1 = acc[im][jn][half * 2 + 1];
                        if (bias) { v0 += bias[col0]; v1 += bias[col0 + 1]; }
                        if (act) { v0 = sp_(v0); v1 = sp_(v1); }
                        *(unsigned*)(((__nv_bfloat16*)C) + (size_t)row * ldc + col0) = pk2(v0, v1);
                    }
                } else {
#pragma unroll
                    for (int cc = 0; cc < 2; cc++) {
                        int col = col0 + cc;
                        if (col >= N) continue;
                        float v = acc[im][jn][half * 2 + cc];
                        if (bias) v += bias[col];
                        if (act) v = sp_(v);
                        C[(size_t)row * ldc + col] = v;
                    }
                }
            }
        }
    }
}

// ---------------- persistent recurrence (bf16 tensor cores, fused input proj) ----------------
struct RP {
    const float* whhp;      // [4][1024*256] permuted
    const float* cihp;      // [2][1024*30]  permuted
    const float* wihp;      // [2][1024*128] permuted
    const float* bp;        // [4][1024]     permuted
    const int*   chars;     // [B][T]
    const float* emb;       // [V][30]
    const float* words;     // [B][WN][128]
    __nv_bfloat16* hbuf;    // bf16 ping-pong
    const int* len_char;
    const int* len_word;
    __nv_bfloat16* outc;
    __nv_bfloat16* outw;
};

// per-(dir,mb) barrier over 16 blocks
__device__ __forceinline__ void grid_bar(int gi, unsigned target) {
    __threadfence();
    __syncthreads();
    if (threadIdx.x == 0) {
        if (atomicAdd(&g_arrs[gi], 1u) == 15u) {
            g_arrs[gi] = 0;
            __threadfence();
            g_gens[gi] = target;
        } else {
            while (g_gens[gi] < target) __nanosleep(32);
        }
    }
    __syncthreads();
}

// smem: Ws [64][132] + As [64][132] + Wxs [64][68] + Xs [64][68] (words)
#define REC_SMEM ((64*132*2 + 64*68*2) * 4)   // 102400 B

__global__ void __launch_bounds__(256, 2) k_rec_persist(RP p) {
    extern __shared__ unsigned smu[];
    unsigned* Ws  = smu;                       // [64][132] Whh tile
    unsigned* As  = Ws  + 64 * 132;            // [64][132] h tile
    unsigned* Wxs = As  + 64 * 132;            // [64][68]  Wih tile
    unsigned* Xs  = Wxs + 64 * 68;             // [64][68]  x tile

    int bx = blockIdx.x;
    int dir = bx >> 6, mb = (bx >> 4) & 3, nb = bx & 15;
    int gi = dir * 4 + mb;
    int tid = threadIdx.x;
    int wid = tid >> 5, lane = tid & 31;
    int gid = lane >> 2, tig = lane & 3;
    int wm = (wid & 3) * 16;
    int wnh = wid >> 2;
    int bm = mb * 64;
    int lr = lane & 15, lc = (lane >> 4) * 4;  // ldmatrix lane addressing

    int Kx  = (dir < 2) ? 30 : 128;
    int Kxw = (dir < 2) ? 16 : 64;
    const float* Wx = (dir < 2) ? (p.cihp + (size_t)dir * 1024 * 30)
                                : (p.wihp + (size_t)(dir - 2) * 1024 * 128);

    // load + pack Whh tile [64 cols][256 k]
    const float* W = p.whhp + (size_t)dir * 1024 * 256;
    for (int idx = tid; idx < 64 * 128; idx += 256) {
        int n = idx >> 7, kw = idx & 127;
        float2 v = *(const float2*)&W[(size_t)(nb * 64 + n) * 256 + kw * 2];
        Ws[n * 132 + kw] = pk2(v.x, v.y);
    }
    // load + pack Wih tile [64 cols][Kx k] (zero-padded to Kxw words)
    for (int idx = tid; idx < 64 * Kxw; idx += 256) {
        int n = idx / Kxw, kw = idx % Kxw;
        const float* wr = Wx + (size_t)(nb * 64 + n) * Kx;
        float lo = (kw * 2     < Kx) ? wr[kw * 2]     : 0.f;
        float hi = (kw * 2 + 1 < Kx) ? wr[kw * 2 + 1] : 0.f;
        Wxs[n * 68 + kw] = pk2(lo, hi);
    }

    // bias fragment: col = nb*64 + wnh*32 + jn*8 + tig*2 + c
    const float* bpd = p.bp + dir * 1024 + nb * 64 + wnh * 32;
    float bias_r[4][2];
#pragma unroll
    for (int jn = 0; jn < 4; jn++) {
        bias_r[jn][0] = bpd[jn * 8 + tig * 2];
        bias_r[jn][1] = bpd[jn * 8 + tig * 2 + 1];
    }

    float hreg[2][2], creg[2][2];
#pragma unroll
    for (int i = 0; i < 2; i++)
#pragma unroll
        for (int j = 0; j < 2; j++) { hreg[i][j] = 0.f; creg[i][j] = 0.f; }

    const int* lens = (dir < 2) ? p.len_char : p.len_word;
    int lenv[2];
    lenv[0] = lens[bm + wm + gid];
    lenv[1] = lens[bm + wm + gid + 8];

    __nv_bfloat16* hb0 = p.hbuf + (size_t)dir * 2 * 65536;
    __nv_bfloat16* hb1 = hb0 + 65536;
    __nv_bfloat16* outp = (dir < 2) ? p.outc : p.outw;
    int half = (dir & 1) ? 256 : 0;

    __syncthreads();

    for (int t = 0; t < TT; t++) {
        int tr = (dir & 1) ? (TT - 1 - t) : t;
        const __nv_bfloat16* h = (t & 1) ? hb1 : hb0;
        __nv_bfloat16* hn_buf = (t & 1) ? hb0 : hb1;

        // stage h tile [64 rows][256 k] — pure uint4 copy (already bf16)
#pragma unroll
        for (int j = 0; j < 8; j++) {
            int q = tid + 256 * j;
            int r = q >> 5, c4 = q & 31;
            uint4 v = __ldcg((const uint4*)&h[(bm + r) * 256 + c4 * 8]);
            *(uint4*)&As[r * 132 + c4 * 4] = v;
        }
        // stage x tile [64 rows][Kx] — read inputs directly
        if (Kxw == 64) {
#pragma unroll
            for (int j = 0; j < 8; j++) {
                int q = tid + 256 * j;
                int r = q >> 5, c4 = q & 31;
                const float* wr = p.words + ((size_t)(bm + r) * TT + tr) * 128 + c4 * 4;
                float4 v = __ldg((const float4*)wr);
                *(uint2*)&Xs[r * 68 + c4 * 2] = make_uint2(pk2(v.x, v.y), pk2(v.z, v.w));
            }
        } else {
#pragma unroll
            for (int j = 0; j < 4; j++) {
                int q = tid + 256 * j;
                int r = q >> 4, kw = q & 15;
                int ci = __ldg(&p.chars[(bm + r) * TT + tr]);
                const float* xr = p.emb + (size_t)ci * 30;
                float lo = (kw * 2     < 30) ? xr[kw * 2]     : 0.f;
                float hi = (kw * 2 + 1 < 30) ? xr[kw * 2 + 1] : 0.f;
                Xs[r * 68 + kw] = pk2(lo, hi);
            }
        }
        __syncthreads();

        float acc[4][4];
#pragma unroll
        for (int j = 0; j < 4; j++)
#pragma unroll
            for (int v = 0; v < 4; v++) acc[j][v] = 0.f;

        // h @ Whh^T (ldmatrix fragments)
#pragma unroll
        for (int ks = 0; ks < 16; ks++) {
            int kw = ks * 8;
            unsigned af[4], b0[4], b1[4];
            ldsm_x4(af, sptr(&As[(wm + lr) * 132 + kw + lc]));
            ldsm_x4(b0, sptr(&Ws[(wnh * 32 + lane) * 132 + kw]));
            ldsm_x4(b1, sptr(&Ws[(wnh * 32 + lane) * 132 + kw + 4]));
#pragma unroll
            for (int jn = 0; jn < 4; jn++) {
                unsigned bb[2] = {b0[jn], b1[jn]};
                mma_bf16(acc[jn], af, bb);
            }
        }
        // x @ Wih^T (fused input projection, ldmatrix fragments)
        int nksx = Kxw >> 3;
#pragma unroll 2
        for (int ks = 0; ks < nksx; ks++) {
            int kw = ks * 8;
            unsigned af[4], b0[4], b1[4];
            ldsm_x4(af, sptr(&Xs[(wm + lr) * 68 + kw + lc]));
            ldsm_x4(b0, sptr(&Wxs[(wnh * 32 + lane) * 68 + kw]));
            ldsm_x4(b1, sptr(&Wxs[(wnh * 32 + lane) * 68 + kw + 4]));
#pragma unroll
            for (int jn = 0; jn < 4; jn++) {
                unsigned bb[2] = {b0[jn], b1[jn]};
                mma_bf16(acc[jn], af, bb);
            }
        }

        // fused LSTM cell epilogue (bias folded); h stored as bf16
#pragma unroll
        for (int rh = 0; rh < 2; rh++) {
            int b = bm + wm + gid + rh * 8;
            bool valid = tr < lenv[rh];
#pragma unroll
            for (int pp = 0; pp < 2; pp++) {
                float gi_ = acc[2 * pp + 0][rh * 2 + 0] + bias_r[2 * pp + 0][0];
                float gf = acc[2 * pp + 0][rh * 2 + 1] + bias_r[2 * pp + 0][1];
                float gc = acc[2 * pp + 1][rh * 2 + 0] + bias_r[2 * pp + 1][0];
                float go = acc[2 * pp + 1][rh * 2 + 1] + bias_r[2 * pp + 1][1];
                float cn = sg_(gf) * creg[rh][pp] + sg_(gi_) * tanhf(gc);
                float hv = sg_(go) * tanhf(cn);
                if (valid) { creg[rh][pp] = cn; hreg[rh][pp] = hv; }
                int u = nb * 16 + wnh * 8 + pp * 4 + tig;
                outp[((size_t)b * TT + tr) * 512 + half + u] = __float2bfloat16(valid ? hv : 0.f);
                hn_buf[b * 256 + u] = __float2bfloat16(hreg[rh][pp]);
            }
        }

        if (t + 1 < TT) grid_bar(gi, (unsigned)(t + 1));
    }
}

// ---------------- CRF: real path score (one warp per batch, deterministic) ----------------
__global__ void k_crf_real(const float* __restrict__ logits, const int* __restrict__ tags,
                           const int* __restrict__ lens, const float* __restrict__ trans,
                           float* __restrict__ rl) {
    __shared__ float st[144];
    int tid = threadIdx.x;
    if (tid < 144) st[tid] = trans[tid];
    __syncthreads();
    int warp = tid >> 5, lane = tid & 31;
    int b = blockIdx.x * 8 + warp;
    int len = lens[b];
    float s = 0.f;
    for (int t = lane; t < len; t += 32) {
        int tg = tags[b * TT + t];
        int prev = (t == 0) ? 10 : tags[b * TT + t - 1];
        s += logits[((size_t)b * TT + t) * 12 + tg] + st[prev * 12 + tg];
    }
#pragma unroll
    for (int o = 16; o > 0; o >>= 1) s += __shfl_xor_sync(0xffffffffu, s, o);
    if (lane == 0) {
        int last = tags[b * TT + len - 1];
        rl[b] = s + st[last * 12 + 11];
    }
}

// ---------------- CRF forward: one warp per batch ----------------
__global__ void k_crf_fwd(const float* __restrict__ logits, const int* __restrict__ lens,
                          const float* __restrict__ trans, float* __restrict__ tot) {
    __shared__ float st[144];
    int tid = threadIdx.x;
    if (tid < 144) st[tid] = trans[tid];
    __syncthreads();
    int warp = tid >> 5, lane = tid & 31;
    int b = blockIdx.x * 8 + warp;
    int len = lens[b];
    float alpha = 0.f;
    for (int t = 0; t < TT; t++) {
        float lt = (lane < 12) ? logits[((size_t)b * TT + t) * 12 + lane] : 0.f;
        float sc[12];
        float mx = -1e30f;
#pragma unroll
        for (int i = 0; i < 12; i++) {
            float ai = __shfl_sync(0xffffffffu, alpha, i);
            float s = ai + ((lane < 12) ? st[i * 12 + lane] : 0.f);
            sc[i] = s;
            mx = fmaxf(mx, s);
        }
        float sm = 0.f;
#pragma unroll
        for (int i = 0; i < 12; i++) sm += expf(sc[i] - mx);
        float an = mx + logf(sm) + lt;
        if (t < len) alpha = an;
    }
    float v = (lane < 12) ? alpha + st[lane * 12 + 11] : -1e30f;
    float mx = v;
#pragma unroll
    for (int o = 16; o > 0; o >>= 1) mx = fmaxf(mx, __shfl_xor_sync(0xffffffffu, mx, o));
    float e = expf(v - mx);
#pragma unroll
    for (int o = 16; o > 0; o >>= 1) e += __shfl_xor_sync(0xffffffffu, e, o);
    if (lane == 0) tot[b] = mx + logf(e);
}

__global__ void k_crf_reduce(const float* __restrict__ crf, float* __restrict__ out) {
    __shared__ float s[256];
    int t = threadIdx.x;
    s[t] = crf[t] - crf[256 + t];
    __syncthreads();
    for (int o = 128; o > 0; o >>= 1) {
        if (t < o) s[t] += s[t + o];
        __syncthreads();
    }
    if (t == 0) out[0] = s[0];
}

// ---------------- launch ----------------
extern "C" void kernel_launch(void* const* d_in, const int* in_sizes, int n_in,
                              void* d_out, int out_size) {
    const int*   characters = (const int*)d_in[0];
    const float* words      = (const float*)d_in[1];
    const int*   tags       = (const int*)d_in[2];
    const int*   len_char   = (const int*)d_in[3];
    const int*   len_word   = (const int*)d_in[4];
    const float* char_emb   = (const float*)d_in[5];
    const float* cWihf = (const float*)d_in[6];
    const float* cWhhf = (const float*)d_in[7];
    const float* cbf   = (const float*)d_in[8];
    const float* cWihb = (const float*)d_in[9];
    const float* cWhhb = (const float*)d_in[10];
    const float* cbb   = (const float*)d_in[11];
    const float* clinW = (const float*)d_in[12];
    const float* clinb = (const float*)d_in[13];
    const float* wWihf = (const float*)d_in[14];
    const float* wWhhf = (const float*)d_in[15];
    const float* wbf   = (const float*)d_in[16];
    const float* wWihb = (const float*)d_in[17];
    const float* wWhhb = (const float*)d_in[18];
    const float* wbb   = (const float*)d_in[19];
    const float* wlinW = (const float*)d_in[20];
    const float* wlinb = (const float*)d_in[21];
    const float* l1W   = (const float*)d_in[22];
    const float* l1b   = (const float*)d_in[23];
    const float* l2W   = (const float*)d_in[24];
    const float* l2b   = (const float*)d_in[25];
    const float* tW    = (const float*)d_in[26];
    const float* tb    = (const float*)d_in[27];
    const float* trans = (const float*)d_in[28];
    float* out = (float*)d_out;

    float *whhp, *cihp, *wihp, *bp, *logits, *crfb;
    __nv_bfloat16 *hbuf, *char_h, *word_h, *xcat, *buf1, *buf2;
    cudaGetSymbolAddress((void**)&whhp,   d_whhp);
    cudaGetSymbolAddress((void**)&cihp,   d_cihp);
    cudaGetSymbolAddress((void**)&wihp,   d_wihp);
    cudaGetSymbolAddress((void**)&bp,     d_bp);
    cudaGetSymbolAddress((void**)&hbuf,   d_hbuf);
    cudaGetSymbolAddress((void**)&char_h, d_char_h);
    cudaGetSymbolAddress((void**)&word_h, d_word_h);
    cudaGetSymbolAddress((void**)&xcat,   d_xcat);
    cudaGetSymbolAddress((void**)&buf1,   d_buf1);
    cudaGetSymbolAddress((void**)&buf2,   d_buf2);
    cudaGetSymbolAddress((void**)&logits, d_logits);
    cudaGetSymbolAddress((void**)&crfb,   d_crf);

    cudaFuncSetAttribute(k_rec_persist, cudaFuncAttributeMaxDynamicSharedMemorySize, REC_SMEM);

    k_init<<<(4 * 2 * BB * 128 + 255) / 256, 256>>>(hbuf);

    // fused weight/bias permutation (12 ops in one launch)
    PrepP pp;
    pp.whh[0] = cWhhf; pp.whh[1] = cWhhb; pp.whh[2] = wWhhf; pp.whh[3] = wWhhb;
    pp.cih[0] = cWihf; pp.cih[1] = cWihb;
    pp.wih[0] = wWihf; pp.wih[1] = wWihb;
    pp.bias[0] = cbf; pp.bias[1] = cbb; pp.bias[2] = wbf; pp.bias[3] = wbb;
    pp.whhp = whhp; pp.cihp = cihp; pp.wihp = wihp; pp.bp = bp;
    k_prep<<<dim3(1024, 12), 256>>>(pp);

    // persistent recurrence with fused input projections; reads raw inputs directly
    RP rp;
    rp.whhp = whhp;
    rp.cihp = cihp;
    rp.wihp = wihp;
    rp.bp   = bp;
    rp.chars = characters;
    rp.emb   = char_emb;
    rp.words = words;
    rp.hbuf = hbuf;
    rp.len_char = len_char;
    rp.len_word = len_word;
    rp.outc = char_h;
    rp.outw = word_h;
    k_rec_persist<<<256, 256, REC_SMEM>>>(rp);

    int Mbt = BB * TT;  // 51200
    auto grid = [](int M, int N) { return dim3((unsigned)((N + 63) / 64), (unsigned)((M + 127) / 128)); };

    // dense stack (bf16 operands, bf16 intermediates, softplus fused)
    k_gemm_tc<<<grid(Mbt, 512), 256>>>(char_h, clinW, clinb, (float*)xcat,         Mbt, 512, 512, 712, 1, 1);
    k_gemm_tc<<<grid(Mbt, 200), 256>>>(word_h, wlinW, wlinb, (float*)(xcat + 512), Mbt, 200, 512, 712, 1, 1);
    k_gemm_tc<<<grid(Mbt, 512), 256>>>(xcat, l1W, l1b, (float*)buf1, Mbt, 512, 712, 512, 1, 1);
    k_gemm_tc<<<grid(Mbt, 256), 256>>>(buf1, l2W, l2b, (float*)buf2, Mbt, 256, 512, 256, 1, 1);
    k_gemm_tc<<<grid(Mbt, 12),  256>>>(buf2, tW,  tb,  logits,       Mbt, 12,  256, 12,  1, 0);

    // CRF
    k_crf_real<<<32, 256>>>(logits, tags, len_char, trans, crfb + BB);
    k_crf_fwd<<<32, 256>>>(logits, len_char, trans, crfb);
    k_crf_reduce<<<1, 256>>>(crfb, out);
}

// round 15
// speedup vs baseline: 1.1003x; 1.0722x over previous
#include <cuda_runtime.h>
#include <cuda_bf16.h>

#define TT 200
#define BB 256

// ---------------- scratch (device globals: allocation-free) ----------------
__device__ float d_whhp[4][1024*256];           // permuted Whh
__device__ float d_cihp[2][1024*30];            // permuted char Wih
__device__ float d_wihp[2][1024*128];           // permuted word Wih
__device__ float d_bp[4][1024];                 // permuted biases
__device__ __nv_bfloat16 d_hbuf[4*2*BB*256];    // ping-pong h per dir (bf16)
__device__ __nv_bfloat16 d_char_h[BB*TT*512];   // [b][t][512] bf16
__device__ __nv_bfloat16 d_word_h[BB*TT*512];   // [b][w][512] bf16
__device__ __nv_bfloat16 d_xcat[BB*TT*736];     // concat bf16 (K padded 712->736)
__device__ __nv_bfloat16 d_buf1[BB*TT*512];
__device__ __nv_bfloat16 d_buf2[BB*TT*256];
__device__ float d_logits[BB*TT*12];
__device__ float d_crf[2*BB];
// pre-converted bf16 dense weights (N padded to 64, K padded to 32)
__device__ __nv_bfloat16 d_wb0[512*512];        // char_lin
__device__ __nv_bfloat16 d_wb1[256*512];        // word_lin (N 200->256)
__device__ __nv_bfloat16 d_wb2[512*736];        // lin1 (K 712->736)
__device__ __nv_bfloat16 d_wb3[256*512];        // lin2
__device__ __nv_bfloat16 d_wb4[64*256];         // tag (N 12->64)

__device__ unsigned g_arrs[16];
__device__ volatile unsigned g_gens[16];

__device__ __forceinline__ float sp_(float x) { return fmaxf(x, 0.f) + log1pf(expf(-fabsf(x))); }
__device__ __forceinline__ float sg_(float x) { return 1.f / (1.f + expf(-x)); }

// pack two fp32 -> bf16x2 word (lo = first element)
__device__ __forceinline__ unsigned pk2(float lo, float hi) {
    unsigned r;
    asm("cvt.rn.bf16x2.f32 %0, %1, %2;" : "=r"(r) : "f"(hi), "f"(lo));
    return r;
}

__device__ __forceinline__ void mma_bf16(float* d, const unsigned* a, const unsigned* b) {
    asm volatile(
        "mma.sync.aligned.m16n8k16.row.col.f32.bf16.bf16.f32 "
        "{%0,%1,%2,%3}, {%4,%5,%6,%7}, {%8,%9}, {%0,%1,%2,%3};\n"
        : "+f"(d[0]), "+f"(d[1]), "+f"(d[2]), "+f"(d[3])
        : "r"(a[0]), "r"(a[1]), "r"(a[2]), "r"(a[3]), "r"(b[0]), "r"(b[1]));
}

__device__ __forceinline__ unsigned sptr(const void* p) {
    return (unsigned)__cvta_generic_to_shared(p);
}

__device__ __forceinline__ void ldsm_x4(unsigned* r, unsigned addr) {
    asm volatile("ldmatrix.sync.aligned.m8n8.x4.shared.b16 {%0,%1,%2,%3}, [%4];"
        : "=r"(r[0]), "=r"(r[1]), "=r"(r[2]), "=r"(r[3]) : "r"(addr));
}

// mma-friendly gate-column permutation: (g,u) -> permuted row index
__device__ __forceinline__ int perm_gu(int g, int u) {
    int nb = u >> 4, w16 = u & 15;
    int h = w16 >> 3, v = w16 & 7;
    int p = v >> 2, t = v & 3;
    return nb * 64 + h * 32 + p * 16 + ((g >> 1) << 3) + t * 2 + (g & 1);
}

// ---------------- init (barriers + hbuf + xcat K-pad) ----------------
__global__ void k_init(__nv_bfloat16* hbuf, __nv_bfloat16* xcat) {
    int i = blockIdx.x * blockDim.x + threadIdx.x;
    if (i < 16) { g_arrs[i] = 0; g_gens[i] = 0; }
    if (i < 262144) ((unsigned*)hbuf)[i] = 0u;       // 524288 bf16
    if (i < 614400) {                                // 51200 rows x 12 pad-words
        int row = i / 12, c = i % 12;
        ((unsigned*)xcat)[row * 368 + 356 + c] = 0u; // cols 712..735
    }
}

struct PrepP {
    const float* whh[4];
    const float* cih[2];
    const float* wih[2];
    const float* bias[4];
    const float* dw[5];                 // clinW, wlinW, l1W, l2W, tW (fp32)
    float* whhp; float* cihp; float* wihp; float* bp;
    __nv_bfloat16* dwb[5];              // bf16 padded outputs
};

// y: 0-3 Whh, 4-5 char Wih, 6-7 word Wih, 8-11 bias, 12-16 dense W -> bf16 padded
__global__ void k_prep(PrepP p) {
    int y = blockIdx.y;
    int i = blockIdx.x * blockDim.x + threadIdx.x;
    if (y < 4) {
        if (i >= 1024 * 256) return;
        int k = i & 255, s = i >> 8;
        int g = s >> 8, u = s & 255;
        p.whhp[(size_t)y * 262144 + perm_gu(g, u) * 256 + k] = p.whh[y][(size_t)s * 256 + k];
    } else if (y < 6) {
        if (i >= 1024 * 30) return;
        int k = i % 30, s = i / 30;
        int g = s >> 8, u = s & 255;
        p.cihp[(size_t)(y - 4) * 30720 + perm_gu(g, u) * 30 + k] = p.cih[y - 4][(size_t)s * 30 + k];
    } else if (y < 8) {
        if (i >= 1024 * 128) return;
        int k = i & 127, s = i >> 7;
        int g = s >> 8, u = s & 255;
        p.wihp[(size_t)(y - 6) * 131072 + perm_gu(g, u) * 128 + k] = p.wih[y - 6][(size_t)s * 128 + k];
    } else if (y < 12) {
        if (i >= 1024) return;
        int g = i >> 8, u = i & 255;
        p.bp[(y - 8) * 1024 + perm_gu(g, u)] = p.bias[y - 8][i];
    } else {
        int w = y - 12;
        const int Ns[5] = {512, 200, 512, 256, 12}, Ks[5] = {512, 512, 712, 512, 256};
        const int Np[5] = {512, 256, 512, 256, 64}, Kp[5] = {512, 512, 736, 512, 256};
        int tot = Np[w] * Kp[w];
        if (i >= tot) return;
        int k = i % Kp[w], n = i / Kp[w];
        float v = (n < Ns[w] && k < Ks[w]) ? p.dw[w][(size_t)n * Ks[w] + k] : 0.f;
        p.dwb[w][(size_t)n * Kp[w] + k] = __float2bfloat16(v);
    }
}

// ---------------- BF16 tensor-core GEMM (double-buffered, guard-free staging) ----------------
// C = act(A[M,K] @ W[N,K]^T + bias); block 128(M) x 64(N); 8 warps 32x32 each.
// A, W bf16; K multiple of 32; W has >= gridDim.x*64 rows (zero-padded).
__global__ void __launch_bounds__(256) k_gemm_tc(
        const __nv_bfloat16* __restrict__ Ab, const __nv_bfloat16* __restrict__ Wb,
        const float* __restrict__ bias, float* __restrict__ C,
        int M, int N, int K, int ldc, int act, int obf) {
    __shared__ unsigned As[2][128][20];
    __shared__ unsigned Bs[2][64][20];

    int tid = threadIdx.x;
    int bm = blockIdx.y * 128, bn = blockIdx.x * 64;
    int wid = tid >> 5, lane = tid & 31;
    int wm = (wid & 3) * 32, wn = (wid >> 2) * 32;
    int gid = lane >> 2, tig = lane & 3;
    int lr = lane & 15, lc = (lane >> 4) * 4;

    float acc[2][4][4];
#pragma unroll
    for (int i = 0; i < 2; i++)
#pragma unroll
        for (int j = 0; j < 4; j++)
#pragma unroll
            for (int v = 0; v < 4; v++) acc[i][j][v] = 0.f;

    // per-thread staging addresses (loop-invariant)
    int ra0 = tid >> 2, rc = (tid & 3) * 4;             // A row (0..63 per j), word col
    const __nv_bfloat16* aptr0 = Ab + (size_t)(bm + ra0) * K + rc * 2;
    const __nv_bfloat16* aptr1 = Ab + (size_t)(bm + ra0 + 64) * K + rc * 2;
    const __nv_bfloat16* wptr  = Wb + (size_t)(bn + ra0) * K + rc * 2;

    uint4 rau[2], rwu;
    auto load_stage = [&](int k0) {
        rau[0] = *(const uint4*)(aptr0 + k0);
        rau[1] = *(const uint4*)(aptr1 + k0);
        rwu    = *(const uint4*)(wptr + k0);
    };
    auto store_stage = [&](int s) {
        *(uint4*)&As[s][ra0][rc]      = rau[0];
        *(uint4*)&As[s][ra0 + 64][rc] = rau[1];
        *(uint4*)&Bs[s][ra0][rc]      = rwu;
    };

    int nch = K >> 5;
    load_stage(0);
    store_stage(0);
    if (nch > 1) load_stage(32);
    __syncthreads();

    for (int i = 0; i < nch; i++) {
        if (i + 1 < nch) {
            store_stage((i + 1) & 1);
            if (i + 2 < nch) load_stage((i + 2) * 32);
        }
        int s = i & 1;
#pragma unroll
        for (int ks = 0; ks < 2; ks++) {
            int kw = ks * 8;
            unsigned af[2][4], b0[4], b1[4];
#pragma unroll
            for (int im = 0; im < 2; im++)
                ldsm_x4(af[im], sptr(&As[s][wm + im * 16 + lr][kw + lc]));
            ldsm_x4(b0, sptr(&Bs[s][wn + lane][kw]));
            ldsm_x4(b1, sptr(&Bs[s][wn + lane][kw + 4]));
#pragma unroll
            for (int im = 0; im < 2; im++)
#pragma unroll
                for (int jn = 0; jn < 4; jn++) {
                    unsigned bb[2] = {b0[jn], b1[jn]};
                    mma_bf16(acc[im][jn], af[im], bb);
                }
        }
        __syncthreads();
    }

#pragma unroll
    for (int im = 0; im < 2; im++) {
#pragma unroll
        for (int jn = 0; jn < 4; jn++) {
            int row0 = bm + wm + im * 16 + gid;
            int col0 = bn + wn + jn * 8 + tig * 2;
#pragma unroll
            for (int half = 0; half < 2; half++) {
                int row = row0 + half * 8;
                if (obf) {
                    if (col0 < N) {
                        float v0 = acc[im][jn][half * 2 + 0];
                        float v1 = acc[im][jn][half * 2 + 1];
                        if (bias) { v0 += bias[col0]; v1 += bias[col0 + 1]; }
                        if (act) { v0 = sp_(v0); v1 = sp_(v1); }
                        *(unsigned*)(((__nv_bfloat16*)C) + (size_t)row * ldc + col0) = pk2(v0, v1);
                    }
                } else {
#pragma unroll
                    for (int cc = 0; cc < 2; cc++) {
                        int col = col0 + cc;
                        if (col >= N) continue;
                        float v = acc[im][jn][half * 2 + cc];
                        if (bias) v += bias[col];
                        if (act) v = sp_(v);
                        C[(size_t)row * ldc + col] = v;
                    }
                }
            }
        }
    }
}

// ---------------- persistent recurrence (bf16 tensor cores, fused input proj) ----------------
struct RP {
    const float* whhp;
    const float* cihp;
    const float* wihp;
    const float* bp;
    const int*   chars;
    const float* emb;
    const float* words;
    __nv_bfloat16* hbuf;
    const int* len_char;
    const int* len_word;
    __nv_bfloat16* outc;
    __nv_bfloat16* outw;
};

__device__ __forceinline__ void grid_bar(int gi, unsigned target) {
    __threadfence();
    __syncthreads();
    if (threadIdx.x == 0) {
        if (atomicAdd(&g_arrs[gi], 1u) == 15u) {
            g_arrs[gi] = 0;
            __threadfence();
            g_gens[gi] = target;
        } else {
            while (g_gens[gi] < target) __nanosleep(32);
        }
    }
    __syncthreads();
}

#define REC_SMEM ((64*132*2 + 64*68*2) * 4)   // 102400 B

__global__ void __launch_bounds__(256, 2) k_rec_persist(RP p) {
    extern __shared__ unsigned smu[];
    unsigned* Ws  = smu;
    unsigned* As  = Ws  + 64 * 132;
    unsigned* Wxs = As  + 64 * 132;
    unsigned* Xs  = Wxs + 64 * 68;

    int bx = blockIdx.x;
    int dir = bx >> 6, mb = (bx >> 4) & 3, nb = bx & 15;
    int gi = dir * 4 + mb;
    int tid = threadIdx.x;
    int wid = tid >> 5, lane = tid & 31;
    int gid = lane >> 2, tig = lane & 3;
    int wm = (wid & 3) * 16;
    int wnh = wid >> 2;
    int bm = mb * 64;
    int lr = lane & 15, lc = (lane >> 4) * 4;

    int Kx  = (dir < 2) ? 30 : 128;
    int Kxw = (dir < 2) ? 16 : 64;
    const float* Wx = (dir < 2) ? (p.cihp + (size_t)dir * 1024 * 30)
                                : (p.wihp + (size_t)(dir - 2) * 1024 * 128);

    const float* W = p.whhp + (size_t)dir * 1024 * 256;
    for (int idx = tid; idx < 64 * 128; idx += 256) {
        int n = idx >> 7, kw = idx & 127;
        float2 v = *(const float2*)&W[(size_t)(nb * 64 + n) * 256 + kw * 2];
        Ws[n * 132 + kw] = pk2(v.x, v.y);
    }
    for (int idx = tid; idx < 64 * Kxw; idx += 256) {
        int n = idx / Kxw, kw = idx % Kxw;
        const float* wr = Wx + (size_t)(nb * 64 + n) * Kx;
        float lo = (kw * 2     < Kx) ? wr[kw * 2]     : 0.f;
        float hi = (kw * 2 + 1 < Kx) ? wr[kw * 2 + 1] : 0.f;
        Wxs[n * 68 + kw] = pk2(lo, hi);
    }

    const float* bpd = p.bp + dir * 1024 + nb * 64 + wnh * 32;
    float bias_r[4][2];
#pragma unroll
    for (int jn = 0; jn < 4; jn++) {
        bias_r[jn][0] = bpd[jn * 8 + tig * 2];
        bias_r[jn][1] = bpd[jn * 8 + tig * 2 + 1];
    }

    float hreg[2][2], creg[2][2];
#pragma unroll
    for (int i = 0; i < 2; i++)
#pragma unroll
        for (int j = 0; j < 2; j++) { hreg[i][j] = 0.f; creg[i][j] = 0.f; }

    const int* lens = (dir < 2) ? p.len_char : p.len_word;
    int lenv[2];
    lenv[0] = lens[bm + wm + gid];
    lenv[1] = lens[bm + wm + gid + 8];

    __nv_bfloat16* hb0 = p.hbuf + (size_t)dir * 2 * 65536;
    __nv_bfloat16* hb1 = hb0 + 65536;
    __nv_bfloat16* outp = (dir < 2) ? p.outc : p.outw;
    int half = (dir & 1) ? 256 : 0;

    __syncthreads();

    for (int t = 0; t < TT; t++) {
        int tr = (dir & 1) ? (TT - 1 - t) : t;
        const __nv_bfloat16* h = (t & 1) ? hb1 : hb0;
        __nv_bfloat16* hn_buf = (t & 1) ? hb0 : hb1;

#pragma unroll
        for (int j = 0; j < 8; j++) {
            int q = tid + 256 * j;
            int r = q >> 5, c4 = q & 31;
            uint4 v = __ldcg((const uint4*)&h[(bm + r) * 256 + c4 * 8]);
            *(uint4*)&As[r * 132 + c4 * 4] = v;
        }
        if (Kxw == 64) {
#pragma unroll
            for (int j = 0; j < 8; j++) {
                int q = tid + 256 * j;
                int r = q >> 5, c4 = q & 31;
                const float* wr = p.words + ((size_t)(bm + r) * TT + tr) * 128 + c4 * 4;
                float4 v = __ldg((const float4*)wr);
                *(uint2*)&Xs[r * 68 + c4 * 2] = make_uint2(pk2(v.x, v.y), pk2(v.z, v.w));
            }
        } else {
#pragma unroll
            for (int j = 0; j < 4; j++) {
                int q = tid + 256 * j;
                int r = q >> 4, kw = q & 15;
                int ci = __ldg(&p.chars[(bm + r) * TT + tr]);
                const float* xr = p.emb + (size_t)ci * 30;
                float lo = (kw * 2     < 30) ? xr[kw * 2]     : 0.f;
                float hi = (kw * 2 + 1 < 30) ? xr[kw * 2 + 1] : 0.f;
                Xs[r * 68 + kw] = pk2(lo, hi);
            }
        }
        __syncthreads();

        float acc[4][4];
#pragma unroll
        for (int j = 0; j < 4; j++)
#pragma unroll
            for (int v = 0; v < 4; v++) acc[j][v] = 0.f;

#pragma unroll
        for (int ks = 0; ks < 16; ks++) {
            int kw = ks * 8;
            unsigned af[4], b0[4], b1[4];
            ldsm_x4(af, sptr(&As[(wm + lr) * 132 + kw + lc]));
            ldsm_x4(b0, sptr(&Ws[(wnh * 32 + lane) * 132 + kw]));
            ldsm_x4(b1, sptr(&Ws[(wnh * 32 + lane) * 132 + kw + 4]));
#pragma unroll
            for (int jn = 0; jn < 4; jn++) {
                unsigned bb[2] = {b0[jn], b1[jn]};
                mma_bf16(acc[jn], af, bb);
            }
        }
        int nksx = Kxw >> 3;
#pragma unroll 2
        for (int ks = 0; ks < nksx; ks++) {
            int kw = ks * 8;
            unsigned af[4], b0[4], b1[4];
            ldsm_x4(af, sptr(&Xs[(wm + lr) * 68 + kw + lc]));
            ldsm_x4(b0, sptr(&Wxs[(wnh * 32 + lane) * 68 + kw]));
            ldsm_x4(b1, sptr(&Wxs[(wnh * 32 + lane) * 68 + kw + 4]));
#pragma unroll
            for (int jn = 0; jn < 4; jn++) {
                unsigned bb[2] = {b0[jn], b1[jn]};
                mma_bf16(acc[jn], af, bb);
            }
        }

#pragma unroll
        for (int rh = 0; rh < 2; rh++) {
            int b = bm + wm + gid + rh * 8;
            bool valid = tr < lenv[rh];
#pragma unroll
            for (int pp = 0; pp < 2; pp++) {
                float gi_ = acc[2 * pp + 0][rh * 2 + 0] + bias_r[2 * pp + 0][0];
                float gf = acc[2 * pp + 0][rh * 2 + 1] + bias_r[2 * pp + 0][1];
                float gc = acc[2 * pp + 1][rh * 2 + 0] + bias_r[2 * pp + 1][0];
                float go = acc[2 * pp + 1][rh * 2 + 1] + bias_r[2 * pp + 1][1];
                float cn = sg_(gf) * creg[rh][pp] + sg_(gi_) * tanhf(gc);
                float hv = sg_(go) * tanhf(cn);
                if (valid) { creg[rh][pp] = cn; hreg[rh][pp] = hv; }
                int u = nb * 16 + wnh * 8 + pp * 4 + tig;
                outp[((size_t)b * TT + tr) * 512 + half + u] = __float2bfloat16(valid ? hv : 0.f);
                hn_buf[b * 256 + u] = __float2bfloat16(hreg[rh][pp]);
            }
        }

        if (t + 1 < TT) grid_bar(gi, (unsigned)(t + 1));
    }
}

// ---------------- CRF ----------------
__global__ void k_crf_real(const float* __restrict__ logits, const int* __restrict__ tags,
                           const int* __restrict__ lens, const float* __restrict__ trans,
                           float* __restrict__ rl) {
    __shared__ float st[144];
    int tid = threadIdx.x;
    if (tid < 144) st[tid] = trans[tid];
    __syncthreads();
    int warp = tid >> 5, lane = tid & 31;
    int b = blockIdx.x * 8 + warp;
    int len = lens[b];
    float s = 0.f;
    for (int t = lane; t < len; t += 32) {
        int tg = tags[b * TT + t];
        int prev = (t == 0) ? 10 : tags[b * TT + t - 1];
        s += logits[((size_t)b * TT + t) * 12 + tg] + st[prev * 12 + tg];
    }
#pragma unroll
    for (int o = 16; o > 0; o >>= 1) s += __shfl_xor_sync(0xffffffffu, s, o);
    if (lane == 0) {
        int last = tags[b * TT + len - 1];
        rl[b] = s + st[last * 12 + 11];
    }
}

__global__ void k_crf_fwd(const float* __restrict__ logits, const int* __restrict__ lens,
                          const float* __restrict__ trans, float* __restrict__ tot) {
    __shared__ float st[144];
    int tid = threadIdx.x;
    if (tid < 144) st[tid] = trans[tid];
    __syncthreads();
    int warp = tid >> 5, lane = tid & 31;
    int b = blockIdx.x * 8 + warp;
    int len = lens[b];
    float alpha = 0.f;
    for (int t = 0; t < TT; t++) {
        float lt = (lane < 12) ? logits[((size_t)b * TT + t) * 12 + lane] : 0.f;
        float sc[12];
        float mx = -1e30f;
#pragma unroll
        for (int i = 0; i < 12; i++) {
            float ai = __shfl_sync(0xffffffffu, alpha, i);
            float s = ai + ((lane < 12) ? st[i * 12 + lane] : 0.f);
            sc[i] = s;
            mx = fmaxf(mx, s);
        }
        float sm = 0.f;
#pragma unroll
        for (int i = 0; i < 12; i++) sm += expf(sc[i] - mx);
        float an = mx + logf(sm) + lt;
        if (t < len) alpha = an;
    }
    float v = (lane < 12) ? alpha + st[lane * 12 + 11] : -1e30f;
    float mx = v;
#pragma unroll
    for (int o = 16; o > 0; o >>= 1) mx = fmaxf(mx, __shfl_xor_sync(0xffffffffu, mx, o));
    float e = expf(v - mx);
#pragma unroll
    for (int o = 16; o > 0; o >>= 1) e += __shfl_xor_sync(0xffffffffu, e, o);
    if (lane == 0) tot[b] = mx + logf(e);
}

__global__ void k_crf_reduce(const float* __restrict__ crf, float* __restrict__ out) {
    __shared__ float s[256];
    int t = threadIdx.x;
    s[t] = crf[t] - crf[256 + t];
    __syncthreads();
    for (int o = 128; o > 0; o >>= 1) {
        if (t < o) s[t] += s[t + o];
        __syncthreads();
    }
    if (t == 0) out[0] = s[0];
}

// ---------------- launch ----------------
extern "C" void kernel_launch(void* const* d_in, const int* in_sizes, int n_in,
                              void* d_out, int out_size) {
    const int*   characters = (const int*)d_in[0];
    const float* words      = (const float*)d_in[1];
    const int*   tags       = (const int*)d_in[2];
    const int*   len_char   = (const int*)d_in[3];
    const int*   len_word   = (const int*)d_in[4];
    const float* char_emb   = (const float*)d_in[5];
    const float* cWihf = (const float*)d_in[6];
    const float* cWhhf = (const float*)d_in[7];
    const float* cbf   = (const float*)d_in[8];
    const float* cWihb = (const float*)d_in[9];
    const float* cWhhb = (const float*)d_in[10];
    const float* cbb   = (const float*)d_in[11];
    const float* clinW = (const float*)d_in[12];
    const float* clinb = (const float*)d_in[13];
    const float* wWihf = (const float*)d_in[14];
    const float* wWhhf = (const float*)d_in[15];
    const float* wbf   = (const float*)d_in[16];
    const float* wWihb = (const float*)d_in[17];
    const float* wWhhb = (const float*)d_in[18];
    const float* wbb   = (const float*)d_in[19];
    const float* wlinW = (const float*)d_in[20];
    const float* wlinb = (const float*)d_in[21];
    const float* l1W   = (const float*)d_in[22];
    const float* l1b   = (const float*)d_in[23];
    const float* l2W   = (const float*)d_in[24];
    const float* l2b   = (const float*)d_in[25];
    const float* tW    = (const float*)d_in[26];
    const float* tb    = (const float*)d_in[27];
    const float* trans = (const float*)d_in[28];
    float* out = (float*)d_out;

    float *whhp, *cihp, *wihp, *bp, *logits, *crfb;
    __nv_bfloat16 *hbuf, *char_h, *word_h, *xcat, *buf1, *buf2;
    __nv_bfloat16 *wb0, *wb1, *wb2, *wb3, *wb4;
    cudaGetSymbolAddress((void**)&whhp,   d_whhp);
    cudaGetSymbolAddress((void**)&cihp,   d_cihp);
    cudaGetSymbolAddress((void**)&wihp,   d_wihp);
    cudaGetSymbolAddress((void**)&bp,     d_bp);
    cudaGetSymbolAddress((void**)&hbuf,   d_hbuf);
    cudaGetSymbolAddress((void**)&char_h, d_char_h);
    cudaGetSymbolAddress((void**)&word_h, d_word_h);
    cudaGetSymbolAddress((void**)&xcat,   d_xcat);
    cudaGetSymbolAddress((void**)&buf1,   d_buf1);
    cudaGetSymbolAddress((void**)&buf2,   d_buf2);
    cudaGetSymbolAddress((void**)&logits, d_logits);
    cudaGetSymbolAddress((void**)&crfb,   d_crf);
    cudaGetSymbolAddress((void**)&wb0,    d_wb0);
    cudaGetSymbolAddress((void**)&wb1,    d_wb1);
    cudaGetSymbolAddress((void**)&wb2,    d_wb2);
    cudaGetSymbolAddress((void**)&wb3,    d_wb3);
    cudaGetSymbolAddress((void**)&wb4,    d_wb4);

    cudaFuncSetAttribute(k_rec_persist, cudaFuncAttributeMaxDynamicSharedMemorySize, REC_SMEM);

    k_init<<<(614400 + 255) / 256, 256>>>(hbuf, xcat);

    // fused weight/bias permutation + dense-weight bf16 conversion (17 ops, one launch)
    PrepP pp;
    pp.whh[0] = cWhhf; pp.whh[1] = cWhhb; pp.whh[2] = wWhhf; pp.whh[3] = wWhhb;
    pp.cih[0] = cWihf; pp.cih[1] = cWihb;
    pp.wih[0] = wWihf; pp.wih[1] = wWihb;
    pp.bias[0] = cbf; pp.bias[1] = cbb; pp.bias[2] = wbf; pp.bias[3] = wbb;
    pp.dw[0] = clinW; pp.dw[1] = wlinW; pp.dw[2] = l1W; pp.dw[3] = l2W; pp.dw[4] = tW;
    pp.whhp = whhp; pp.cihp = cihp; pp.wihp = wihp; pp.bp = bp;
    pp.dwb[0] = wb0; pp.dwb[1] = wb1; pp.dwb[2] = wb2; pp.dwb[3] = wb3; pp.dwb[4] = wb4;
    k_prep<<<dim3(1472, 17), 256>>>(pp);

    // persistent recurrence with fused input projections
    RP rp;
    rp.whhp = whhp;
    rp.cihp = cihp;
    rp.wihp = wihp;
    rp.bp   = bp;
    rp.chars = characters;
    rp.emb   = char_emb;
    rp.words = words;
    rp.hbuf = hbuf;
    rp.len_char = len_char;
    rp.len_word = len_word;
    rp.outc = char_h;
    rp.outw = word_h;
    k_rec_persist<<<256, 256, REC_SMEM>>>(rp);

    int Mbt = BB * TT;  // 51200
    auto grid = [](int M, int N) { return dim3((unsigned)((N + 63) / 64), (unsigned)((M + 127) / 128)); };

    // dense stack (bf16 A and W, guard-free staging; xcat ldc=736, K padded)
    k_gemm_tc<<<grid(Mbt, 512), 256>>>(char_h, wb0, clinb, (float*)xcat,         Mbt, 512, 512, 736, 1, 1);
    k_gemm_tc<<<grid(Mbt, 200), 256>>>(word_h, wb1, wlinb, (float*)(xcat + 512), Mbt, 200, 512, 736, 1, 1);
    k_gemm_tc<<<grid(Mbt, 512), 256>>>(xcat, wb2, l1b, (float*)buf1, Mbt, 512, 736, 512, 1, 1);
    k_gemm_tc<<<grid(Mbt, 256), 256>>>(buf1, wb3, l2b, (float*)buf2, Mbt, 256, 512, 256, 1, 1);
    k_gemm_tc<<<grid(Mbt, 12),  256>>>(buf2, wb4, tb,  logits,       Mbt, 12,  256, 12,  1, 0);

    // CRF
    k_crf_real<<<32, 256>>>(logits, tags, len_char, trans, crfb + BB);
    k_crf_fwd<<<32, 256>>>(logits, len_char, trans, crfb);
    k_crf_reduce<<<1, 256>>>(crfb, out);
}

// round 16
// speedup vs baseline: 1.1034x; 1.0029x over previous
#include <cuda_runtime.h>
#include <cuda_bf16.h>

#define TT 200
#define BB 256

// ---------------- scratch (device globals: allocation-free) ----------------
__device__ float d_whhp[4][1024*256];           // permuted Whh
__device__ float d_cihp[2][1024*30];            // permuted char Wih
__device__ float d_wihp[2][1024*128];           // permuted word Wih
__device__ float d_bp[4][1024];                 // permuted biases
__device__ __nv_bfloat16 d_hbuf[4*2*BB*256];    // ping-pong h per dir (bf16)
__device__ __nv_bfloat16 d_char_h[BB*TT*512];   // [b][t][512] bf16
__device__ __nv_bfloat16 d_word_h[BB*TT*512];   // [b][w][512] bf16
__device__ __nv_bfloat16 d_xcat[BB*TT*736];     // concat bf16 (K padded 712->736)
__device__ __nv_bfloat16 d_buf1[BB*TT*512];
__device__ __nv_bfloat16 d_buf2[BB*TT*256];
__device__ float d_logits[BB*TT*12];
__device__ float d_crf[2*BB];
// pre-converted bf16 dense weights (N padded to 64, K padded to 32)
__device__ __nv_bfloat16 d_wb0[512*512];        // char_lin
__device__ __nv_bfloat16 d_wb1[256*512];        // word_lin (N 200->256)
__device__ __nv_bfloat16 d_wb2[512*736];        // lin1 (K 712->736)
__device__ __nv_bfloat16 d_wb3[256*512];        // lin2
__device__ __nv_bfloat16 d_wb4[64*256];         // tag (N 12->64)

__device__ unsigned g_arrs[16];
__device__ volatile unsigned g_gens[16];

__device__ __forceinline__ float sp_(float x) { return fmaxf(x, 0.f) + log1pf(expf(-fabsf(x))); }
__device__ __forceinline__ float sg_(float x) { return 1.f / (1.f + expf(-x)); }

// pack two fp32 -> bf16x2 word (lo = first element)
__device__ __forceinline__ unsigned pk2(float lo, float hi) {
    unsigned r;
    asm("cvt.rn.bf16x2.f32 %0, %1, %2;" : "=r"(r) : "f"(hi), "f"(lo));
    return r;
}

__device__ __forceinline__ void mma_bf16(float* d, const unsigned* a, const unsigned* b) {
    asm volatile(
        "mma.sync.aligned.m16n8k16.row.col.f32.bf16.bf16.f32 "
        "{%0,%1,%2,%3}, {%4,%5,%6,%7}, {%8,%9}, {%0,%1,%2,%3};\n"
        : "+f"(d[0]), "+f"(d[1]), "+f"(d[2]), "+f"(d[3])
        : "r"(a[0]), "r"(a[1]), "r"(a[2]), "r"(a[3]), "r"(b[0]), "r"(b[1]));
}

__device__ __forceinline__ unsigned sptr(const void* p) {
    return (unsigned)__cvta_generic_to_shared(p);
}

__device__ __forceinline__ void ldsm_x4(unsigned* r, unsigned addr) {
    asm volatile("ldmatrix.sync.aligned.m8n8.x4.shared.b16 {%0,%1,%2,%3}, [%4];"
        : "=r"(r[0]), "=r"(r[1]), "=r"(r[2]), "=r"(r[3]) : "r"(addr));
}

// mma-friendly gate-column permutation: (g,u) -> permuted row index
__device__ __forceinline__ int perm_gu(int g, int u) {
    int nb = u >> 4, w16 = u & 15;
    int h = w16 >> 3, v = w16 & 7;
    int p = v >> 2, t = v & 3;
    return nb * 64 + h * 32 + p * 16 + ((g >> 1) << 3) + t * 2 + (g & 1);
}

// ---------------- init (barriers + hbuf + xcat K-pad) ----------------
__global__ void k_init(__nv_bfloat16* hbuf, __nv_bfloat16* xcat) {
    int i = blockIdx.x * blockDim.x + threadIdx.x;
    if (i < 16) { g_arrs[i] = 0; g_gens[i] = 0; }
    if (i < 262144) ((unsigned*)hbuf)[i] = 0u;       // 524288 bf16
    if (i < 614400) {                                // 51200 rows x 12 pad-words
        int row = i / 12, c = i % 12;
        ((unsigned*)xcat)[row * 368 + 356 + c] = 0u; // cols 712..735
    }
}

struct PrepP {
    const float* whh[4];
    const float* cih[2];
    const float* wih[2];
    const float* bias[4];
    const float* dw[5];                 // clinW, wlinW, l1W, l2W, tW (fp32)
    float* whhp; float* cihp; float* wihp; float* bp;
    __nv_bfloat16* dwb[5];              // bf16 padded outputs
};

// y: 0-3 Whh, 4-5 char Wih, 6-7 word Wih, 8-11 bias, 12-16 dense W -> bf16 padded
__global__ void k_prep(PrepP p) {
    int y = blockIdx.y;
    int i = blockIdx.x * blockDim.x + threadIdx.x;
    if (y < 4) {
        if (i >= 1024 * 256) return;
        int k = i & 255, s = i >> 8;
        int g = s >> 8, u = s & 255;
        p.whhp[(size_t)y * 262144 + perm_gu(g, u) * 256 + k] = p.whh[y][(size_t)s * 256 + k];
    } else if (y < 6) {
        if (i >= 1024 * 30) return;
        int k = i % 30, s = i / 30;
        int g = s >> 8, u = s & 255;
        p.cihp[(size_t)(y - 4) * 30720 + perm_gu(g, u) * 30 + k] = p.cih[y - 4][(size_t)s * 30 + k];
    } else if (y < 8) {
        if (i >= 1024 * 128) return;
        int k = i & 127, s = i >> 7;
        int g = s >> 8, u = s & 255;
        p.wihp[(size_t)(y - 6) * 131072 + perm_gu(g, u) * 128 + k] = p.wih[y - 6][(size_t)s * 128 + k];
    } else if (y < 12) {
        if (i >= 1024) return;
        int g = i >> 8, u = i & 255;
        p.bp[(y - 8) * 1024 + perm_gu(g, u)] = p.bias[y - 8][i];
    } else {
        int w = y - 12;
        const int Ns[5] = {512, 200, 512, 256, 12}, Ks[5] = {512, 512, 712, 512, 256};
        const int Np[5] = {512, 256, 512, 256, 64}, Kp[5] = {512, 512, 736, 512, 256};
        int tot = Np[w] * Kp[w];
        if (i >= tot) return;
        int k = i % Kp[w], n = i / Kp[w];
        float v = (n < Ns[w] && k < Ks[w]) ? p.dw[w][(size_t)n * Ks[w] + k] : 0.f;
        p.dwb[w][(size_t)n * Kp[w] + k] = __float2bfloat16(v);
    }
}

// ---------------- BF16 tensor-core GEMM (block 256x64, warp 64x32, dbl-buffered) ----------------
// C = act(A[M,K] @ W[N,K]^T + bias); M multiple of 256; K multiple of 32;
// W zero-padded to gridDim.x*64 rows.
#define GEMM_SMEM ((2*256*20 + 2*64*20) * 4)   // 51200 B

__global__ void __launch_bounds__(256) k_gemm_tc(
        const __nv_bfloat16* __restrict__ Ab, const __nv_bfloat16* __restrict__ Wb,
        const float* __restrict__ bias, float* __restrict__ C,
        int M, int N, int K, int ldc, int act, int obf) {
    extern __shared__ unsigned smg[];
    unsigned* As = smg;                 // [2][256][20]
    unsigned* Bs = smg + 2 * 256 * 20;  // [2][64][20]

    int tid = threadIdx.x;
    int bm = blockIdx.y * 256, bn = blockIdx.x * 64;
    int wid = tid >> 5, lane = tid & 31;
    int wm = (wid & 3) * 64, wn = (wid >> 2) * 32;
    int gid = lane >> 2, tig = lane & 3;
    int lr = lane & 15, lc = (lane >> 4) * 4;

    float acc[4][4][4];
#pragma unroll
    for (int i = 0; i < 4; i++)
#pragma unroll
        for (int j = 0; j < 4; j++)
#pragma unroll
            for (int v = 0; v < 4; v++) acc[i][j][v] = 0.f;

    // per-thread staging addresses (loop-invariant)
    int ra0 = tid >> 2, rc = (tid & 3) * 4;             // row (0..63 per j), word col
    const __nv_bfloat16* aptr[4];
#pragma unroll
    for (int j = 0; j < 4; j++) aptr[j] = Ab + (size_t)(bm + ra0 + 64 * j) * K + rc * 2;
    const __nv_bfloat16* wptr = Wb + (size_t)(bn + ra0) * K + rc * 2;

    uint4 rau[4], rwu;
    auto load_stage = [&](int k0) {
#pragma unroll
        for (int j = 0; j < 4; j++) rau[j] = *(const uint4*)(aptr[j] + k0);
        rwu = *(const uint4*)(wptr + k0);
    };
    auto store_stage = [&](int s) {
#pragma unroll
        for (int j = 0; j < 4; j++)
            *(uint4*)&As[(s * 256 + ra0 + 64 * j) * 20 + rc] = rau[j];
        *(uint4*)&Bs[(s * 64 + ra0) * 20 + rc] = rwu;
    };

    int nch = K >> 5;
    load_stage(0);
    store_stage(0);
    if (nch > 1) load_stage(32);
    __syncthreads();

    for (int i = 0; i < nch; i++) {
        if (i + 1 < nch) {
            store_stage((i + 1) & 1);
            if (i + 2 < nch) load_stage((i + 2) * 32);
        }
        int s = i & 1;
#pragma unroll
        for (int ks = 0; ks < 2; ks++) {
            int kw = ks * 8;
            unsigned af[4][4], b0[4], b1[4];
#pragma unroll
            for (int im = 0; im < 4; im++)
                ldsm_x4(af[im], sptr(&As[(s * 256 + wm + im * 16 + lr) * 20 + kw + lc]));
            ldsm_x4(b0, sptr(&Bs[(s * 64 + wn + lane) * 20 + kw]));
            ldsm_x4(b1, sptr(&Bs[(s * 64 + wn + lane) * 20 + kw + 4]));
#pragma unroll
            for (int im = 0; im < 4; im++)
#pragma unroll
                for (int jn = 0; jn < 4; jn++) {
                    unsigned bb[2] = {b0[jn], b1[jn]};
                    mma_bf16(acc[im][jn], af[im], bb);
                }
        }
        __syncthreads();
    }

#pragma unroll
    for (int im = 0; im < 4; im++) {
#pragma unroll
        for (int jn = 0; jn < 4; jn++) {
            int row0 = bm + wm + im * 16 + gid;
            int col0 = bn + wn + jn * 8 + tig * 2;
#pragma unroll
            for (int half = 0; half < 2; half++) {
                int row = row0 + half * 8;
                if (obf) {
                    if (col0 < N) {
                        float v0 = acc[im][jn][half * 2 + 0];
                        float v1 = acc[im][jn][half * 2 + 1];
                        if (bias) { v0 += bias[col0]; v1 += bias[col0 + 1]; }
                        if (act) { v0 = sp_(v0); v1 = sp_(v1); }
                        *(unsigned*)(((__nv_bfloat16*)C) + (size_t)row * ldc + col0) = pk2(v0, v1);
                    }
                } else {
#pragma unroll
                    for (int cc = 0; cc < 2; cc++) {
                        int col = col0 + cc;
                        if (col >= N) continue;
                        float v = acc[im][jn][half * 2 + cc];
                        if (bias) v += bias[col];
                        if (act) v = sp_(v);
                        C[(size_t)row * ldc + col] = v;
                    }
                }
            }
        }
    }
}

// ---------------- persistent recurrence (bf16 tensor cores, fused input proj) ----------------
struct RP {
    const float* whhp;
    const float* cihp;
    const float* wihp;
    const float* bp;
    const int*   chars;
    const float* emb;
    const float* words;
    __nv_bfloat16* hbuf;
    const int* len_char;
    const int* len_word;
    __nv_bfloat16* outc;
    __nv_bfloat16* outw;
};

__device__ __forceinline__ void grid_bar(int gi, unsigned target) {
    __threadfence();
    __syncthreads();
    if (threadIdx.x == 0) {
        if (atomicAdd(&g_arrs[gi], 1u) == 15u) {
            g_arrs[gi] = 0;
            __threadfence();
            g_gens[gi] = target;
        } else {
            while (g_gens[gi] < target) __nanosleep(32);
        }
    }
    __syncthreads();
}

#define REC_SMEM ((64*132*2 + 64*68*2) * 4)   // 102400 B

__global__ void __launch_bounds__(256, 2) k_rec_persist(RP p) {
    extern __shared__ unsigned smu[];
    unsigned* Ws  = smu;
    unsigned* As  = Ws  + 64 * 132;
    unsigned* Wxs = As  + 64 * 132;
    unsigned* Xs  = Wxs + 64 * 68;

    int bx = blockIdx.x;
    int dir = bx >> 6, mb = (bx >> 4) & 3, nb = bx & 15;
    int gi = dir * 4 + mb;
    int tid = threadIdx.x;
    int wid = tid >> 5, lane = tid & 31;
    int gid = lane >> 2, tig = lane & 3;
    int wm = (wid & 3) * 16;
    int wnh = wid >> 2;
    int bm = mb * 64;
    int lr = lane & 15, lc = (lane >> 4) * 4;

    int Kx  = (dir < 2) ? 30 : 128;
    int Kxw = (dir < 2) ? 16 : 64;
    const float* Wx = (dir < 2) ? (p.cihp + (size_t)dir * 1024 * 30)
                                : (p.wihp + (size_t)(dir - 2) * 1024 * 128);

    const float* W = p.whhp + (size_t)dir * 1024 * 256;
    for (int idx = tid; idx < 64 * 128; idx += 256) {
        int n = idx >> 7, kw = idx & 127;
        float2 v = *(const float2*)&W[(size_t)(nb * 64 + n) * 256 + kw * 2];
        Ws[n * 132 + kw] = pk2(v.x, v.y);
    }
    for (int idx = tid; idx < 64 * Kxw; idx += 256) {
        int n = idx / Kxw, kw = idx % Kxw;
        const float* wr = Wx + (size_t)(nb * 64 + n) * Kx;
        float lo = (kw * 2     < Kx) ? wr[kw * 2]     : 0.f;
        float hi = (kw * 2 + 1 < Kx) ? wr[kw * 2 + 1] : 0.f;
        Wxs[n * 68 + kw] = pk2(lo, hi);
    }

    const float* bpd = p.bp + dir * 1024 + nb * 64 + wnh * 32;
    float bias_r[4][2];
#pragma unroll
    for (int jn = 0; jn < 4; jn++) {
        bias_r[jn][0] = bpd[jn * 8 + tig * 2];
        bias_r[jn][1] = bpd[jn * 8 + tig * 2 + 1];
    }

    float hreg[2][2], creg[2][2];
#pragma unroll
    for (int i = 0; i < 2; i++)
#pragma unroll
        for (int j = 0; j < 2; j++) { hreg[i][j] = 0.f; creg[i][j] = 0.f; }

    const int* lens = (dir < 2) ? p.len_char : p.len_word;
    int lenv[2];
    lenv[0] = lens[bm + wm + gid];
    lenv[1] = lens[bm + wm + gid + 8];

    __nv_bfloat16* hb0 = p.hbuf + (size_t)dir * 2 * 65536;
    __nv_bfloat16* hb1 = hb0 + 65536;
    __nv_bfloat16* outp = (dir < 2) ? p.outc : p.outw;
    int half = (dir & 1) ? 256 : 0;

    __syncthreads();

    for (int t = 0; t < TT; t++) {
        int tr = (dir & 1) ? (TT - 1 - t) : t;
        const __nv_bfloat16* h = (t & 1) ? hb1 : hb0;
        __nv_bfloat16* hn_buf = (t & 1) ? hb0 : hb1;

#pragma unroll
        for (int j = 0; j < 8; j++) {
            int q = tid + 256 * j;
            int r = q >> 5, c4 = q & 31;
            uint4 v = __ldcg((const uint4*)&h[(bm + r) * 256 + c4 * 8]);
            *(uint4*)&As[r * 132 + c4 * 4] = v;
        }
        if (Kxw == 64) {
#pragma unroll
            for (int j = 0; j < 8; j++) {
                int q = tid + 256 * j;
                int r = q >> 5, c4 = q & 31;
                const float* wr = p.words + ((size_t)(bm + r) * TT + tr) * 128 + c4 * 4;
                float4 v = __ldg((const float4*)wr);
                *(uint2*)&Xs[r * 68 + c4 * 2] = make_uint2(pk2(v.x, v.y), pk2(v.z, v.w));
            }
        } else {
#pragma unroll
            for (int j = 0; j < 4; j++) {
                int q = tid + 256 * j;
                int r = q >> 4, kw = q & 15;
                int ci = __ldg(&p.chars[(bm + r) * TT + tr]);
                const float* xr = p.emb + (size_t)ci * 30;
                float lo = (kw * 2     < 30) ? xr[kw * 2]     : 0.f;
                float hi = (kw * 2 + 1 < 30) ? xr[kw * 2 + 1] : 0.f;
                Xs[r * 68 + kw] = pk2(lo, hi);
            }
        }
        __syncthreads();

        float acc[4][4];
#pragma unroll
        for (int j = 0; j < 4; j++)
#pragma unroll
            for (int v = 0; v < 4; v++) acc[j][v] = 0.f;

#pragma unroll
        for (int ks = 0; ks < 16; ks++) {
            int kw = ks * 8;
            unsigned af[4], b0[4], b1[4];
            ldsm_x4(af, sptr(&As[(wm + lr) * 132 + kw + lc]));
            ldsm_x4(b0, sptr(&Ws[(wnh * 32 + lane) * 132 + kw]));
            ldsm_x4(b1, sptr(&Ws[(wnh * 32 + lane) * 132 + kw + 4]));
#pragma unroll
            for (int jn = 0; jn < 4; jn++) {
                unsigned bb[2] = {b0[jn], b1[jn]};
                mma_bf16(acc[jn], af, bb);
            }
        }
        int nksx = Kxw >> 3;
#pragma unroll 2
        for (int ks = 0; ks < nksx; ks++) {
            int kw = ks * 8;
            unsigned af[4], b0[4], b1[4];
            ldsm_x4(af, sptr(&Xs[(wm + lr) * 68 + kw + lc]));
            ldsm_x4(b0, sptr(&Wxs[(wnh * 32 + lane) * 68 + kw]));
            ldsm_x4(b1, sptr(&Wxs[(wnh * 32 + lane) * 68 + kw + 4]));
#pragma unroll
            for (int jn = 0; jn < 4; jn++) {
                unsigned bb[2] = {b0[jn], b1[jn]};
                mma_bf16(acc[jn], af, bb);
            }
        }

#pragma unroll
        for (int rh = 0; rh < 2; rh++) {
            int b = bm + wm + gid + rh * 8;
            bool valid = tr < lenv[rh];
#pragma unroll
            for (int pp = 0; pp < 2; pp++) {
                float gi_ = acc[2 * pp + 0][rh * 2 + 0] + bias_r[2 * pp + 0][0];
                float gf = acc[2 * pp + 0][rh * 2 + 1] + bias_r[2 * pp + 0][1];
                float gc = acc[2 * pp + 1][rh * 2 + 0] + bias_r[2 * pp + 1][0];
                float go = acc[2 * pp + 1][rh * 2 + 1] + bias_r[2 * pp + 1][1];
                float cn = sg_(gf) * creg[rh][pp] + sg_(gi_) * tanhf(gc);
                float hv = sg_(go) * tanhf(cn);
                if (valid) { creg[rh][pp] = cn; hreg[rh][pp] = hv; }
                int u = nb * 16 + wnh * 8 + pp * 4 + tig;
                outp[((size_t)b * TT + tr) * 512 + half + u] = __float2bfloat16(valid ? hv : 0.f);
                hn_buf[b * 256 + u] = __float2bfloat16(hreg[rh][pp]);
            }
        }

        if (t + 1 < TT) grid_bar(gi, (unsigned)(t + 1));
    }
}

// ---------------- CRF ----------------
__global__ void k_crf_real(const float* __restrict__ logits, const int* __restrict__ tags,
                           const int* __restrict__ lens, const float* __restrict__ trans,
                           float* __restrict__ rl) {
    __shared__ float st[144];
    int tid = threadIdx.x;
    if (tid < 144) st[tid] = trans[tid];
    __syncthreads();
    int warp = tid >> 5, lane = tid & 31;
    int b = blockIdx.x * 8 + warp;
    int len = lens[b];
    float s = 0.f;
    for (int t = lane; t < len; t += 32) {
        int tg = tags[b * TT + t];
        int prev = (t == 0) ? 10 : tags[b * TT + t - 1];
        s += logits[((size_t)b * TT + t) * 12 + tg] + st[prev * 12 + tg];
    }
#pragma unroll
    for (int o = 16; o > 0; o >>= 1) s += __shfl_xor_sync(0xffffffffu, s, o);
    if (lane == 0) {
        int last = tags[b * TT + len - 1];
        rl[b] = s + st[last * 12 + 11];
    }
}

__global__ void k_crf_fwd(const float* __restrict__ logits, const int* __restrict__ lens,
                          const float* __restrict__ trans, float* __restrict__ tot) {
    __shared__ float st[144];
    int tid = threadIdx.x;
    if (tid < 144) st[tid] = trans[tid];
    __syncthreads();
    int warp = tid >> 5, lane = tid & 31;
    int b = blockIdx.x * 8 + warp;
    int len = lens[b];
    float alpha = 0.f;
    for (int t = 0; t < TT; t++) {
        float lt = (lane < 12) ? logits[((size_t)b * TT + t) * 12 + lane] : 0.f;
        float sc[12];
        float mx = -1e30f;
#pragma unroll
        for (int i = 0; i < 12; i++) {
            float ai = __shfl_sync(0xffffffffu, alpha, i);
            float s = ai + ((lane < 12) ? st[i * 12 + lane] : 0.f);
            sc[i] = s;
            mx = fmaxf(mx, s);
        }
        float sm = 0.f;
#pragma unroll
        for (int i = 0; i < 12; i++) sm += expf(sc[i] - mx);
        float an = mx + logf(sm) + lt;
        if (t < len) alpha = an;
    }
    float v = (lane < 12) ? alpha + st[lane * 12 + 11] : -1e30f;
    float mx = v;
#pragma unroll
    for (int o = 16; o > 0; o >>= 1) mx = fmaxf(mx, __shfl_xor_sync(0xffffffffu, mx, o));
    float e = expf(v - mx);
#pragma unroll
    for (int o = 16; o > 0; o >>= 1) e += __shfl_xor_sync(0xffffffffu, e, o);
    if (lane == 0) tot[b] = mx + logf(e);
}

__global__ void k_crf_reduce(const float* __restrict__ crf, float* __restrict__ out) {
    __shared__ float s[256];
    int t = threadIdx.x;
    s[t] = crf[t] - crf[256 + t];
    __syncthreads();
    for (int o = 128; o > 0; o >>= 1) {
        if (t < o) s[t] += s[t + o];
        __syncthreads();
    }
    if (t == 0) out[0] = s[0];
}

// ---------------- launch ----------------
extern "C" void kernel_launch(void* const* d_in, const int* in_sizes, int n_in,
                              void* d_out, int out_size) {
    const int*   characters = (const int*)d_in[0];
    const float* words      = (const float*)d_in[1];
    const int*   tags       = (const int*)d_in[2];
    const int*   len_char   = (const int*)d_in[3];
    const int*   len_word   = (const int*)d_in[4];
    const float* char_emb   = (const float*)d_in[5];
    const float* cWihf = (const float*)d_in[6];
    const float* cWhhf = (const float*)d_in[7];
    const float* cbf   = (const float*)d_in[8];
    const float* cWihb = (const float*)d_in[9];
    const float* cWhhb = (const float*)d_in[10];
    const float* cbb   = (const float*)d_in[11];
    const float* clinW = (const float*)d_in[12];
    const float* clinb = (const float*)d_in[13];
    const float* wWihf = (const float*)d_in[14];
    const float* wWhhf = (const float*)d_in[15];
    const float* wbf   = (const float*)d_in[16];
    const float* wWihb = (const float*)d_in[17];
    const float* wWhhb = (const float*)d_in[18];
    const float* wbb   = (const float*)d_in[19];
    const float* wlinW = (const float*)d_in[20];
    const float* wlinb = (const float*)d_in[21];
    const float* l1W   = (const float*)d_in[22];
    const float* l1b   = (const float*)d_in[23];
    const float* l2W   = (const float*)d_in[24];
    const float* l2b   = (const float*)d_in[25];
    const float* tW    = (const float*)d_in[26];
    const float* tb    = (const float*)d_in[27];
    const float* trans = (const float*)d_in[28];
    float* out = (float*)d_out;

    float *whhp, *cihp, *wihp, *bp, *logits, *crfb;
    __nv_bfloat16 *hbuf, *char_h, *word_h, *xcat, *buf1, *buf2;
    __nv_bfloat16 *wb0, *wb1, *wb2, *wb3, *wb4;
    cudaGetSymbolAddress((void**)&whhp,   d_whhp);
    cudaGetSymbolAddress((void**)&cihp,   d_cihp);
    cudaGetSymbolAddress((void**)&wihp,   d_wihp);
    cudaGetSymbolAddress((void**)&bp,     d_bp);
    cudaGetSymbolAddress((void**)&hbuf,   d_hbuf);
    cudaGetSymbolAddress((void**)&char_h, d_char_h);
    cudaGetSymbolAddress((void**)&word_h, d_word_h);
    cudaGetSymbolAddress((void**)&xcat,   d_xcat);
    cudaGetSymbolAddress((void**)&buf1,   d_buf1);
    cudaGetSymbolAddress((void**)&buf2,   d_buf2);
    cudaGetSymbolAddress((void**)&logits, d_logits);
    cudaGetSymbolAddress((void**)&crfb,   d_crf);
    cudaGetSymbolAddress((void**)&wb0,    d_wb0);
    cudaGetSymbolAddress((void**)&wb1,    d_wb1);
    cudaGetSymbolAddress((void**)&wb2,    d_wb2);
    cudaGetSymbolAddress((void**)&wb3,    d_wb3);
    cudaGetSymbolAddress((void**)&wb4,    d_wb4);

    cudaFuncSetAttribute(k_rec_persist, cudaFuncAttributeMaxDynamicSharedMemorySize, REC_SMEM);
    cudaFuncSetAttribute(k_gemm_tc, cudaFuncAttributeMaxDynamicSharedMemorySize, GEMM_SMEM);

    k_init<<<(614400 + 255) / 256, 256>>>(hbuf, xcat);

    // fused weight/bias permutation + dense-weight bf16 conversion (17 ops, one launch)
    PrepP pp;
    pp.whh[0] = cWhhf; pp.whh[1] = cWhhb; pp.whh[2] = wWhhf; pp.whh[3] = wWhhb;
    pp.cih[0] = cWihf; pp.cih[1] = cWihb;
    pp.wih[0] = wWihf; pp.wih[1] = wWihb;
    pp.bias[0] = cbf; pp.bias[1] = cbb; pp.bias[2] = wbf; pp.bias[3] = wbb;
    pp.dw[0] = clinW; pp.dw[1] = wlinW; pp.dw[2] = l1W; pp.dw[3] = l2W; pp.dw[4] = tW;
    pp.whhp = whhp; pp.cihp = cihp; pp.wihp = wihp; pp.bp = bp;
    pp.dwb[0] = wb0; pp.dwb[1] = wb1; pp.dwb[2] = wb2; pp.dwb[3] = wb3; pp.dwb[4] = wb4;
    k_prep<<<dim3(1472, 17), 256>>>(pp);

    // persistent recurrence with fused input projections
    RP rp;
    rp.whhp = whhp;
    rp.cihp = cihp;
    rp.wihp = wihp;
    rp.bp   = bp;
    rp.chars = characters;
    rp.emb   = char_emb;
    rp.words = words;
    rp.hbuf = hbuf;
    rp.len_char = len_char;
    rp.len_word = len_word;
    rp.outc = char_h;
    rp.outw = word_h;
    k_rec_persist<<<256, 256, REC_SMEM>>>(rp);

    int Mbt = BB * TT;  // 51200
    auto grid = [](int M, int N) { return dim3((unsigned)((N + 63) / 64), (unsigned)((M + 255) / 256)); };

    // dense stack (bf16 A and W, guard-free staging; xcat ldc=736, K padded)
    k_gemm_tc<<<grid(Mbt, 512), 256, GEMM_SMEM>>>(char_h, wb0, clinb, (float*)xcat,         Mbt, 512, 512, 736, 1, 1);
    k_gemm_tc<<<grid(Mbt, 200), 256, GEMM_SMEM>>>(word_h, wb1, wlinb, (float*)(xcat + 512), Mbt, 200, 512, 736, 1, 1);
    k_gemm_tc<<<grid(Mbt, 512), 256, GEMM_SMEM>>>(xcat, wb2, l1b, (float*)buf1, Mbt, 512, 736, 512, 1, 1);
    k_gemm_tc<<<grid(Mbt, 256), 256, GEMM_SMEM>>>(buf1, wb3, l2b, (float*)buf2, Mbt, 256, 512, 256, 1, 1);
    k_gemm_tc<<<grid(Mbt, 12),  256, GEMM_SMEM>>>(buf2, wb4, tb,  logits,       Mbt, 12,  256, 12,  1, 0);

    // CRF
    k_crf_real<<<32, 256>>>(logits, tags, len_char, trans, crfb + BB);
    k_crf_fwd<<<32, 256>>>(logits, len_char, trans, crfb);
    k_crf_reduce<<<1, 256>>>(crfb, out);
}

// round 17
// speedup vs baseline: 1.1230x; 1.0177x over previous
#include <cuda_runtime.h>
#include <cuda_bf16.h>

#define TT 200
#define BB 256

// ---------------- scratch (device globals: allocation-free) ----------------
__device__ float d_whhp[4][1024*256];           // permuted Whh
__device__ float d_cihp[2][1024*30];            // permuted char Wih
__device__ float d_wihp[2][1024*128];           // permuted word Wih
__device__ float d_bp[4][1024];                 // permuted biases
__device__ __nv_bfloat16 d_hbuf[4*2*BB*256];    // ping-pong h per dir (bf16)
__device__ __nv_bfloat16 d_char_h[BB*TT*512];   // [b][t][512] bf16
__device__ __nv_bfloat16 d_word_h[BB*TT*512];   // [b][w][512] bf16
__device__ __nv_bfloat16 d_xcat[BB*TT*736];     // concat bf16 (K padded 712->736)
__device__ __nv_bfloat16 d_buf1[BB*TT*512];
__device__ __nv_bfloat16 d_buf2[BB*TT*256];
__device__ float d_logits[BB*TT*12];
__device__ float d_crf[2*BB];
// pre-converted bf16 dense weights (N padded to 64, K padded to 32)
__device__ __nv_bfloat16 d_wb0[512*512];        // char_lin
__device__ __nv_bfloat16 d_wb1[256*512];        // word_lin (N 200->256)
__device__ __nv_bfloat16 d_wb2[512*736];        // lin1 (K 712->736)
__device__ __nv_bfloat16 d_wb3[256*512];        // lin2
__device__ __nv_bfloat16 d_wb4[64*256];         // tag (N 12->64)

__device__ unsigned g_arrs[16];
__device__ volatile unsigned g_gens[16];

__device__ __forceinline__ float sp_(float x) { return fmaxf(x, 0.f) + log1pf(expf(-fabsf(x))); }
__device__ __forceinline__ float sg_(float x) { return 1.f / (1.f + expf(-x)); }

// pack two fp32 -> bf16x2 word (lo = first element)
__device__ __forceinline__ unsigned pk2(float lo, float hi) {
    unsigned r;
    asm("cvt.rn.bf16x2.f32 %0, %1, %2;" : "=r"(r) : "f"(hi), "f"(lo));
    return r;
}

__device__ __forceinline__ void mma_bf16(float* d, const unsigned* a, const unsigned* b) {
    asm volatile(
        "mma.sync.aligned.m16n8k16.row.col.f32.bf16.bf16.f32 "
        "{%0,%1,%2,%3}, {%4,%5,%6,%7}, {%8,%9}, {%0,%1,%2,%3};\n"
        : "+f"(d[0]), "+f"(d[1]), "+f"(d[2]), "+f"(d[3])
        : "r"(a[0]), "r"(a[1]), "r"(a[2]), "r"(a[3]), "r"(b[0]), "r"(b[1]));
}

__device__ __forceinline__ unsigned sptr(const void* p) {
    return (unsigned)__cvta_generic_to_shared(p);
}

__device__ __forceinline__ void ldsm_x4(unsigned* r, unsigned addr) {
    asm volatile("ldmatrix.sync.aligned.m8n8.x4.shared.b16 {%0,%1,%2,%3}, [%4];"
        : "=r"(r[0]), "=r"(r[1]), "=r"(r[2]), "=r"(r[3]) : "r"(addr));
}

__device__ __forceinline__ void cp16(void* dst, const void* src) {
    asm volatile("cp.async.cg.shared.global [%0], [%1], 16;"
        :: "r"(sptr(dst)), "l"(src));
}
__device__ __forceinline__ void cp_commit() { asm volatile("cp.async.commit_group;"); }
__device__ __forceinline__ void cp_wait0() { asm volatile("cp.async.wait_group 0;"); }
__device__ __forceinline__ void cp_wait1() { asm volatile("cp.async.wait_group 1;"); }

// mma-friendly gate-column permutation: (g,u) -> permuted row index
__device__ __forceinline__ int perm_gu(int g, int u) {
    int nb = u >> 4, w16 = u & 15;
    int h = w16 >> 3, v = w16 & 7;
    int p = v >> 2, t = v & 3;
    return nb * 64 + h * 32 + p * 16 + ((g >> 1) << 3) + t * 2 + (g & 1);
}

// ---------------- init (barriers + hbuf + xcat K-pad) ----------------
__global__ void k_init(__nv_bfloat16* hbuf, __nv_bfloat16* xcat) {
    int i = blockIdx.x * blockDim.x + threadIdx.x;
    if (i < 16) { g_arrs[i] = 0; g_gens[i] = 0; }
    if (i < 262144) ((unsigned*)hbuf)[i] = 0u;       // 524288 bf16
    if (i < 614400) {                                // 51200 rows x 12 pad-words
        int row = i / 12, c = i % 12;
        ((unsigned*)xcat)[row * 368 + 356 + c] = 0u; // cols 712..735
    }
}

struct PrepP {
    const float* whh[4];
    const float* cih[2];
    const float* wih[2];
    const float* bias[4];
    const float* dw[5];                 // clinW, wlinW, l1W, l2W, tW (fp32)
    float* whhp; float* cihp; float* wihp; float* bp;
    __nv_bfloat16* dwb[5];              // bf16 padded outputs
};

// y: 0-3 Whh, 4-5 char Wih, 6-7 word Wih, 8-11 bias, 12-16 dense W -> bf16 padded
__global__ void k_prep(PrepP p) {
    int y = blockIdx.y;
    int i = blockIdx.x * blockDim.x + threadIdx.x;
    if (y < 4) {
        if (i >= 1024 * 256) return;
        int k = i & 255, s = i >> 8;
        int g = s >> 8, u = s & 255;
        p.whhp[(size_t)y * 262144 + perm_gu(g, u) * 256 + k] = p.whh[y][(size_t)s * 256 + k];
    } else if (y < 6) {
        if (i >= 1024 * 30) return;
        int k = i % 30, s = i / 30;
        int g = s >> 8, u = s & 255;
        p.cihp[(size_t)(y - 4) * 30720 + perm_gu(g, u) * 30 + k] = p.cih[y - 4][(size_t)s * 30 + k];
    } else if (y < 8) {
        if (i >= 1024 * 128) return;
        int k = i & 127, s = i >> 7;
        int g = s >> 8, u = s & 255;
        p.wihp[(size_t)(y - 6) * 131072 + perm_gu(g, u) * 128 + k] = p.wih[y - 6][(size_t)s * 128 + k];
    } else if (y < 12) {
        if (i >= 1024) return;
        int g = i >> 8, u = i & 255;
        p.bp[(y - 8) * 1024 + perm_gu(g, u)] = p.bias[y - 8][i];
    } else {
        int w = y - 12;
        const int Ns[5] = {512, 200, 512, 256, 12}, Ks[5] = {512, 512, 712, 512, 256};
        const int Np[5] = {512, 256, 512, 256, 64}, Kp[5] = {512, 512, 736, 512, 256};
        int tot = Np[w] * Kp[w];
        if (i >= tot) return;
        int k = i % Kp[w], n = i / Kp[w];
        float v = (n < Ns[w] && k < Ks[w]) ? p.dw[w][(size_t)n * Ks[w] + k] : 0.f;
        p.dwb[w][(size_t)n * Kp[w] + k] = __float2bfloat16(v);
    }
}

// ---------------- BF16 tensor-core GEMM (block 256x64, warp 64x32, cp.async 3-stage) ----------------
// C = act(A[M,K] @ W[N,K]^T + bias); M multiple of 256; K multiple of 32;
// W zero-padded to gridDim.x*64 rows.
#define GEMM_STG ((256 + 64) * 20)
#define GEMM_SMEM (3 * GEMM_STG * 4)   // 76800 B

__global__ void __launch_bounds__(256, 2) k_gemm_tc(
        const __nv_bfloat16* __restrict__ Ab, const __nv_bfloat16* __restrict__ Wb,
        const float* __restrict__ bias, float* __restrict__ C,
        int M, int N, int K, int ldc, int act, int obf) {
    extern __shared__ unsigned smg[];

    int tid = threadIdx.x;
    int bm = blockIdx.y * 256, bn = blockIdx.x * 64;
    int wid = tid >> 5, lane = tid & 31;
    int wm = (wid & 3) * 64, wn = (wid >> 2) * 32;
    int gid = lane >> 2, tig = lane & 3;
    int lr = lane & 15, lc = (lane >> 4) * 4;

    float acc[4][4][4];
#pragma unroll
    for (int i = 0; i < 4; i++)
#pragma unroll
        for (int j = 0; j < 4; j++)
#pragma unroll
            for (int v = 0; v < 4; v++) acc[i][j][v] = 0.f;

    int ra0 = tid >> 2, rc = (tid & 3) * 4;
    const __nv_bfloat16* aptr[4];
#pragma unroll
    for (int j = 0; j < 4; j++) aptr[j] = Ab + (size_t)(bm + ra0 + 64 * j) * K + rc * 2;
    const __nv_bfloat16* wptr = Wb + (size_t)(bn + ra0) * K + rc * 2;

    auto issue = [&](int ch) {
        unsigned* As_ = smg + (ch % 3) * GEMM_STG;
        unsigned* Bs_ = As_ + 256 * 20;
        int k0 = ch * 32;
#pragma unroll
        for (int j = 0; j < 4; j++)
            cp16(&As_[(ra0 + 64 * j) * 20 + rc], aptr[j] + k0);
        cp16(&Bs_[ra0 * 20 + rc], wptr + k0);
        cp_commit();
    };

    int nch = K >> 5;
    issue(0);
    if (nch > 1) issue(1);

    for (int i = 0; i < nch; i++) {
        if (i + 1 < nch) cp_wait1(); else cp_wait0();
        __syncthreads();
        if (i + 2 < nch) issue(i + 2);
        unsigned* As_ = smg + (i % 3) * GEMM_STG;
        unsigned* Bs_ = As_ + 256 * 20;
#pragma unroll
        for (int ks = 0; ks < 2; ks++) {
            int kw = ks * 8;
            unsigned af[4][4], b0[4], b1[4];
#pragma unroll
            for (int im = 0; im < 4; im++)
                ldsm_x4(af[im], sptr(&As_[(wm + im * 16 + lr) * 20 + kw + lc]));
            ldsm_x4(b0, sptr(&Bs_[(wn + lane) * 20 + kw]));
            ldsm_x4(b1, sptr(&Bs_[(wn + lane) * 20 + kw + 4]));
#pragma unroll
            for (int im = 0; im < 4; im++)
#pragma unroll
                for (int jn = 0; jn < 4; jn++) {
                    unsigned bb[2] = {b0[jn], b1[jn]};
                    mma_bf16(acc[im][jn], af[im], bb);
                }
        }
    }

#pragma unroll
    for (int im = 0; im < 4; im++) {
#pragma unroll
        for (int jn = 0; jn < 4; jn++) {
            int row0 = bm + wm + im * 16 + gid;
            int col0 = bn + wn + jn * 8 + tig * 2;
#pragma unroll
            for (int half = 0; half < 2; half++) {
                int row = row0 + half * 8;
                if (obf) {
                    if (col0 < N) {
                        float v0 = acc[im][jn][half * 2 + 0];
                        float v1 = acc[im][jn][half * 2 + 1];
                        if (bias) { v0 += bias[col0]; v1 += bias[col0 + 1]; }
                        if (act) { v0 = sp_(v0); v1 = sp_(v1); }
                        *(unsigned*)(((__nv_bfloat16*)C) + (size_t)row * ldc + col0) = pk2(v0, v1);
                    }
                } else {
#pragma unroll
                    for (int cc = 0; cc < 2; cc++) {
                        int col = col0 + cc;
                        if (col >= N) continue;
                        float v = acc[im][jn][half * 2 + cc];
                        if (bias) v += bias[col];
                        if (act) v = sp_(v);
                        C[(size_t)row * ldc + col] = v;
                    }
                }
            }
        }
    }
}

// ---------------- persistent recurrence (bf16 tensor cores, fused input proj) ----------------
struct RP {
    const float* whhp;
    const float* cihp;
    const float* wihp;
    const float* bp;
    const int*   chars;
    const float* emb;
    const float* words;
    __nv_bfloat16* hbuf;
    const int* len_char;
    const int* len_word;
    __nv_bfloat16* outc;
    __nv_bfloat16* outw;
};

__device__ __forceinline__ void grid_bar(int gi, unsigned target) {
    __threadfence();
    __syncthreads();
    if (threadIdx.x == 0) {
        if (atomicAdd(&g_arrs[gi], 1u) == 15u) {
            g_arrs[gi] = 0;
            __threadfence();
            g_gens[gi] = target;
        } else {
            while (g_gens[gi] < target) __nanosleep(32);
        }
    }
    __syncthreads();
}

#define REC_SMEM ((64*132*2 + 64*68*2) * 4)   // 102400 B

__global__ void __launch_bounds__(256, 2) k_rec_persist(RP p) {
    extern __shared__ unsigned smu[];
    unsigned* Ws  = smu;
    unsigned* As  = Ws  + 64 * 132;
    unsigned* Wxs = As  + 64 * 132;
    unsigned* Xs  = Wxs + 64 * 68;

    int bx = blockIdx.x;
    int dir = bx >> 6, mb = (bx >> 4) & 3, nb = bx & 15;
    int gi = dir * 4 + mb;
    int tid = threadIdx.x;
    int wid = tid >> 5, lane = tid & 31;
    int gid = lane >> 2, tig = lane & 3;
    int wm = (wid & 3) * 16;
    int wnh = wid >> 2;
    int bm = mb * 64;
    int lr = lane & 15, lc = (lane >> 4) * 4;

    int Kx  = (dir < 2) ? 30 : 128;
    int Kxw = (dir < 2) ? 16 : 64;
    const float* Wx = (dir < 2) ? (p.cihp + (size_t)dir * 1024 * 30)
                                : (p.wihp + (size_t)(dir - 2) * 1024 * 128);

    const float* W = p.whhp + (size_t)dir * 1024 * 256;
    for (int idx = tid; idx < 64 * 128; idx += 256) {
        int n = idx >> 7, kw = idx & 127;
        float2 v = *(const float2*)&W[(size_t)(nb * 64 + n) * 256 + kw * 2];
        Ws[n * 132 + kw] = pk2(v.x, v.y);
    }
    for (int idx = tid; idx < 64 * Kxw; idx += 256) {
        int n = idx / Kxw, kw = idx % Kxw;
        const float* wr = Wx + (size_t)(nb * 64 + n) * Kx;
        float lo = (kw * 2     < Kx) ? wr[kw * 2]     : 0.f;
        float hi = (kw * 2 + 1 < Kx) ? wr[kw * 2 + 1] : 0.f;
        Wxs[n * 68 + kw] = pk2(lo, hi);
    }

    const float* bpd = p.bp + dir * 1024 + nb * 64 + wnh * 32;
    float bias_r[4][2];
#pragma unroll
    for (int jn = 0; jn < 4; jn++) {
        bias_r[jn][0] = bpd[jn * 8 + tig * 2];
        bias_r[jn][1] = bpd[jn * 8 + tig * 2 + 1];
    }

    float hreg[2][2], creg[2][2];
#pragma unroll
    for (int i = 0; i < 2; i++)
#pragma unroll
        for (int j = 0; j < 2; j++) { hreg[i][j] = 0.f; creg[i][j] = 0.f; }

    const int* lens = (dir < 2) ? p.len_char : p.len_word;
    int lenv[2];
    lenv[0] = lens[bm + wm + gid];
    lenv[1] = lens[bm + wm + gid + 8];

    __nv_bfloat16* hb0 = p.hbuf + (size_t)dir * 2 * 65536;
    __nv_bfloat16* hb1 = hb0 + 65536;
    __nv_bfloat16* outp = (dir < 2) ? p.outc : p.outw;
    int half = (dir & 1) ? 256 : 0;

    __syncthreads();

    for (int t = 0; t < TT; t++) {
        int tr = (dir & 1) ? (TT - 1 - t) : t;
        const __nv_bfloat16* h = (t & 1) ? hb1 : hb0;
        __nv_bfloat16* hn_buf = (t & 1) ? hb0 : hb1;

        // stage h tile via cp.async (no register round-trip)
#pragma unroll
        for (int j = 0; j < 8; j++) {
            int q = tid + 256 * j;
            int r = q >> 5, c4 = q & 31;
            cp16(&As[r * 132 + c4 * 4], &h[(bm + r) * 256 + c4 * 8]);
        }
        cp_commit();
        // x staging overlaps the cp.async
        if (Kxw == 64) {
#pragma unroll
            for (int j = 0; j < 8; j++) {
                int q = tid + 256 * j;
                int r = q >> 5, c4 = q & 31;
                const float* wr = p.words + ((size_t)(bm + r) * TT + tr) * 128 + c4 * 4;
                float4 v = __ldg((const float4*)wr);
                *(uint2*)&Xs[r * 68 + c4 * 2] = make_uint2(pk2(v.x, v.y), pk2(v.z, v.w));
            }
        } else {
#pragma unroll
            for (int j = 0; j < 4; j++) {
                int q = tid + 256 * j;
                int r = q >> 4, kw = q & 15;
                int ci = __ldg(&p.chars[(bm + r) * TT + tr]);
                const float* xr = p.emb + (size_t)ci * 30;
                float lo = (kw * 2     < 30) ? xr[kw * 2]     : 0.f;
                float hi = (kw * 2 + 1 < 30) ? xr[kw * 2 + 1] : 0.f;
                Xs[r * 68 + kw] = pk2(lo, hi);
            }
        }
        cp_wait0();
        __syncthreads();

        float acc[4][4];
#pragma unroll
        for (int j = 0; j < 4; j++)
#pragma unroll
            for (int v = 0; v < 4; v++) acc[j][v] = 0.f;

#pragma unroll
        for (int ks = 0; ks < 16; ks++) {
            int kw = ks * 8;
            unsigned af[4], b0[4], b1[4];
            ldsm_x4(af, sptr(&As[(wm + lr) * 132 + kw + lc]));
            ldsm_x4(b0, sptr(&Ws[(wnh * 32 + lane) * 132 + kw]));
            ldsm_x4(b1, sptr(&Ws[(wnh * 32 + lane) * 132 + kw + 4]));
#pragma unroll
            for (int jn = 0; jn < 4; jn++) {
                unsigned bb[2] = {b0[jn], b1[jn]};
                mma_bf16(acc[jn], af, bb);
            }
        }
        int nksx = Kxw >> 3;
#pragma unroll 2
        for (int ks = 0; ks < nksx; ks++) {
            int kw = ks * 8;
            unsigned af[4], b0[4], b1[4];
            ldsm_x4(af, sptr(&Xs[(wm + lr) * 68 + kw + lc]));
            ldsm_x4(b0, sptr(&Wxs[(wnh * 32 + lane) * 68 + kw]));
            ldsm_x4(b1, sptr(&Wxs[(wnh * 32 + lane) * 68 + kw + 4]));
#pragma unroll
            for (int jn = 0; jn < 4; jn++) {
                unsigned bb[2] = {b0[jn], b1[jn]};
                mma_bf16(acc[jn], af, bb);
            }
        }

#pragma unroll
        for (int rh = 0; rh < 2; rh++) {
            int b = bm + wm + gid + rh * 8;
            bool valid = tr < lenv[rh];
#pragma unroll
            for (int pp = 0; pp < 2; pp++) {
                float gi_ = acc[2 * pp + 0][rh * 2 + 0] + bias_r[2 * pp + 0][0];
                float gf = acc[2 * pp + 0][rh * 2 + 1] + bias_r[2 * pp + 0][1];
                float gc = acc[2 * pp + 1][rh * 2 + 0] + bias_r[2 * pp + 1][0];
                float go = acc[2 * pp + 1][rh * 2 + 1] + bias_r[2 * pp + 1][1];
                float cn = sg_(gf) * creg[rh][pp] + sg_(gi_) * tanhf(gc);
                float hv = sg_(go) * tanhf(cn);
                if (valid) { creg[rh][pp] = cn; hreg[rh][pp] = hv; }
                int u = nb * 16 + wnh * 8 + pp * 4 + tig;
                outp[((size_t)b * TT + tr) * 512 + half + u] = __float2bfloat16(valid ? hv : 0.f);
                hn_buf[b * 256 + u] = __float2bfloat16(hreg[rh][pp]);
            }
        }

        if (t + 1 < TT) grid_bar(gi, (unsigned)(t + 1));
    }
}

// ---------------- CRF ----------------
__global__ void k_crf_real(const float* __restrict__ logits, const int* __restrict__ tags,
                           const int* __restrict__ lens, const float* __restrict__ trans,
                           float* __restrict__ rl) {
    __shared__ float st[144];
    int tid = threadIdx.x;
    if (tid < 144) st[tid] = trans[tid];
    __syncthreads();
    int warp = tid >> 5, lane = tid & 31;
    int b = blockIdx.x * 8 + warp;
    int len = lens[b];
    float s = 0.f;
    for (int t = lane; t < len; t += 32) {
        int tg = tags[b * TT + t];
        int prev = (t == 0) ? 10 : tags[b * TT + t - 1];
        s += logits[((size_t)b * TT + t) * 12 + tg] + st[prev * 12 + tg];
    }
#pragma unroll
    for (int o = 16; o > 0; o >>= 1) s += __shfl_xor_sync(0xffffffffu, s, o);
    if (lane == 0) {
        int last = tags[b * TT + len - 1];
        rl[b] = s + st[last * 12 + 11];
    }
}

__global__ void k_crf_fwd(const float* __restrict__ logits, const int* __restrict__ lens,
                          const float* __restrict__ trans, float* __restrict__ tot) {
    __shared__ float st[144];
    int tid = threadIdx.x;
    if (tid < 144) st[tid] = trans[tid];
    __syncthreads();
    int warp = tid >> 5, lane = tid & 31;
    int b = blockIdx.x * 8 + warp;
    int len = lens[b];
    float alpha = 0.f;
    for (int t = 0; t < TT; t++) {
        float lt = (lane < 12) ? logits[((size_t)b * TT + t) * 12 + lane] : 0.f;
        float sc[12];
        float mx = -1e30f;
#pragma unroll
        for (int i = 0; i < 12; i++) {
            float ai = __shfl_sync(0xffffffffu, alpha, i);
            float s = ai + ((lane < 12) ? st[i * 12 + lane] : 0.f);
            sc[i] = s;
            mx = fmaxf(mx, s);
        }
        float sm = 0.f;
#pragma unroll
        for (int i = 0; i < 12; i++) sm += expf(sc[i] - mx);
        float an = mx + logf(sm) + lt;
        if (t < len) alpha = an;
    }
    float v = (lane < 12) ? alpha + st[lane * 12 + 11] : -1e30f;
    float mx = v;
#pragma unroll
    for (int o = 16; o > 0; o >>= 1) mx = fmaxf(mx, __shfl_xor_sync(0xffffffffu, mx, o));
    float e = expf(v - mx);
#pragma unroll
    for (int o = 16; o > 0; o >>= 1) e += __shfl_xor_sync(0xffffffffu, e, o);
    if (lane == 0) tot[b] = mx + logf(e);
}

__global__ void k_crf_reduce(const float* __restrict__ crf, float* __restrict__ out) {
    __shared__ float s[256];
    int t = threadIdx.x;
    s[t] = crf[t] - crf[256 + t];
    __syncthreads();
    for (int o = 128; o > 0; o >>= 1) {
        if (t < o) s[t] += s[t + o];
        __syncthreads();
    }
    if (t == 0) out[0] = s[0];
}

// ---------------- launch ----------------
extern "C" void kernel_launch(void* const* d_in, const int* in_sizes, int n_in,
                              void* d_out, int out_size) {
    const int*   characters = (const int*)d_in[0];
    const float* words      = (const float*)d_in[1];
    const int*   tags       = (const int*)d_in[2];
    const int*   len_char   = (const int*)d_in[3];
    const int*   len_word   = (const int*)d_in[4];
    const float* char_emb   = (const float*)d_in[5];
    const float* cWihf = (const float*)d_in[6];
    const float* cWhhf = (const float*)d_in[7];
    const float* cbf   = (const float*)d_in[8];
    const float* cWihb = (const float*)d_in[9];
    const float* cWhhb = (const float*)d_in[10];
    const float* cbb   = (const float*)d_in[11];
    const float* clinW = (const float*)d_in[12];
    const float* clinb = (const float*)d_in[13];
    const float* wWihf = (const float*)d_in[14];
    const float* wWhhf = (const float*)d_in[15];
    const float* wbf   = (const float*)d_in[16];
    const float* wWihb = (const float*)d_in[17];
    const float* wWhhb = (const float*)d_in[18];
    const float* wbb   = (const float*)d_in[19];
    const float* wlinW = (const float*)d_in[20];
    const float* wlinb = (const float*)d_in[21];
    const float* l1W   = (const float*)d_in[22];
    const float* l1b   = (const float*)d_in[23];
    const float* l2W   = (const float*)d_in[24];
    const float* l2b   = (const float*)d_in[25];
    const float* tW    = (const float*)d_in[26];
    const float* tb    = (const float*)d_in[27];
    const float* trans = (const float*)d_in[28];
    float* out = (float*)d_out;

    float *whhp, *cihp, *wihp, *bp, *logits, *crfb;
    __nv_bfloat16 *hbuf, *char_h, *word_h, *xcat, *buf1, *buf2;
    __nv_bfloat16 *wb0, *wb1, *wb2, *wb3, *wb4;
    cudaGetSymbolAddress((void**)&whhp,   d_whhp);
    cudaGetSymbolAddress((void**)&cihp,   d_cihp);
    cudaGetSymbolAddress((void**)&wihp,   d_wihp);
    cudaGetSymbolAddress((void**)&bp,     d_bp);
    cudaGetSymbolAddress((void**)&hbuf,   d_hbuf);
    cudaGetSymbolAddress((void**)&char_h, d_char_h);
    cudaGetSymbolAddress((void**)&word_h, d_word_h);
    cudaGetSymbolAddress((void**)&xcat,   d_xcat);
    cudaGetSymbolAddress((void**)&buf1,   d_buf1);
    cudaGetSymbolAddress((void**)&buf2,   d_buf2);
    cudaGetSymbolAddress((void**)&logits, d_logits);
    cudaGetSymbolAddress((void**)&crfb,   d_crf);
    cudaGetSymbolAddress((void**)&wb0,    d_wb0);
    cudaGetSymbolAddress((void**)&wb1,    d_wb1);
    cudaGetSymbolAddress((void**)&wb2,    d_wb2);
    cudaGetSymbolAddress((void**)&wb3,    d_wb3);
    cudaGetSymbolAddress((void**)&wb4,    d_wb4);

    cudaFuncSetAttribute(k_rec_persist, cudaFuncAttributeMaxDynamicSharedMemorySize, REC_SMEM);
    cudaFuncSetAttribute(k_gemm_tc, cudaFuncAttributeMaxDynamicSharedMemorySize, GEMM_SMEM);

    k_init<<<(614400 + 255) / 256, 256>>>(hbuf, xcat);

    // fused weight/bias permutation + dense-weight bf16 conversion (17 ops, one launch)
    PrepP pp;
    pp.whh[0] = cWhhf; pp.whh[1] = cWhhb; pp.whh[2] = wWhhf; pp.whh[3] = wWhhb;
    pp.cih[0] = cWihf; pp.cih[1] = cWihb;
    pp.wih[0] = wWihf; pp.wih[1] = wWihb;
    pp.bias[0] = cbf; pp.bias[1] = cbb; pp.bias[2] = wbf; pp.bias[3] = wbb;
    pp.dw[0] = clinW; pp.dw[1] = wlinW; pp.dw[2] = l1W; pp.dw[3] = l2W; pp.dw[4] = tW;
    pp.whhp = whhp; pp.cihp = cihp; pp.wihp = wihp; pp.bp = bp;
    pp.dwb[0] = wb0; pp.dwb[1] = wb1; pp.dwb[2] = wb2; pp.dwb[3] = wb3; pp.dwb[4] = wb4;
    k_prep<<<dim3(1472, 17), 256>>>(pp);

    // persistent recurrence with fused input projections
    RP rp;
    rp.whhp = whhp;
    rp.cihp = cihp;
    rp.wihp = wihp;
    rp.bp   = bp;
    rp.chars = characters;
    rp.emb   = char_emb;
    rp.words = words;
    rp.hbuf = hbuf;
    rp.len_char = len_char;
    rp.len_word = len_word;
    rp.outc = char_h;
    rp.outw = word_h;
    k_rec_persist<<<256, 256, REC_SMEM>>>(rp);

    int Mbt = BB * TT;  // 51200
    auto grid = [](int M, int N) { return dim3((unsigned)((N + 63) / 64), (unsigned)((M + 255) / 256)); };

    // dense stack (bf16 A and W, cp.async staging; xcat ldc=736, K padded)
    k_gemm_tc<<<grid(Mbt, 512), 256, GEMM_SMEM>>>(char_h, wb0, clinb, (float*)xcat,         Mbt, 512, 512, 736, 1, 1);
    k_gemm_tc<<<grid(Mbt, 200), 256, GEMM_SMEM>>>(word_h, wb1, wlinb, (float*)(xcat + 512), Mbt, 200, 512, 736, 1, 1);
    k_gemm_tc<<<grid(Mbt, 512), 256, GEMM_SMEM>>>(xcat, wb2, l1b, (float*)buf1, Mbt, 512, 736, 512, 1, 1);
    k_gemm_tc<<<grid(Mbt, 256), 256, GEMM_SMEM>>>(buf1, wb3, l2b, (float*)buf2, Mbt, 256, 512, 256, 1, 1);
    k_gemm_tc<<<grid(Mbt, 12),  256, GEMM_SMEM>>>(buf2, wb4, tb,  logits,       Mbt, 12,  256, 12,  1, 0);

    // CRF
    k_crf_real<<<32, 256>>>(logits, tags, len_char, trans, crfb + BB);
    k_crf_fwd<<<32, 256>>>(logits, len_char, trans, crfb);
    k_crf_reduce<<<1, 256>>>(crfb, out);
}